// round 5
// baseline (speedup 1.0000x reference)
#include <cuda_runtime.h>
#include <math.h>

#define EDGES    800000
#define NNODES   50000
#define HDIM     128
#define K1       384
#define FFDIM    512
#define TE       64
#define TN       64
#define NTHREADS 256
#define XS_STRIDE 388
#define WS_STRIDE 132
#define YS_STRIDE 132
#define Y5_STRIDE 516
#define SCALE_F  30.0f
#define LN_EPS   1e-5f

// Scratch (no allocation allowed): message accumulator + edge counts
__device__ float g_nsum[(size_t)NNODES * HDIM];
__device__ float g_cnt[NNODES];

__device__ __forceinline__ float gelu_exact(float x) {
    return 0.5f * x * (1.0f + erff(x * 0.70710678118654752440f));
}

// Load a 32(K) x 128(N) chunk of W (row-major, rows = 128 outputs, ld = ldw),
// columns k0..k0+31, transposed into ws[32][WS_STRIDE].
__device__ __forceinline__ void load_wchunk(const float* __restrict__ W, int ldw, int k0,
                                            float* ws, int tid) {
#pragma unroll
    for (int t = 0; t < 4; t++) {
        int idx = tid + t * NTHREADS;   // 0..1023
        int r   = idx >> 3;             // output row 0..127
        int c4  = idx & 7;              // which float4 of the 32-wide chunk
        float4 v = *(const float4*)(W + (size_t)r * ldw + k0 + c4 * 4);
        int kl = c4 * 4;
        ws[(kl + 0) * WS_STRIDE + r] = v.x;
        ws[(kl + 1) * WS_STRIDE + r] = v.y;
        ws[(kl + 2) * WS_STRIDE + r] = v.z;
        ws[(kl + 3) * WS_STRIDE + r] = v.w;
    }
}

// acc[4 rows][8 outs] += xsrc[row][kk] * ws[kk][out], kk = 0..31
__device__ __forceinline__ void gemm_accum(const float* xsrc, int xstride, const float* ws,
                                           float acc[4][8], int er4, int oc8) {
    const float* x0 = xsrc + (er4 + 0) * xstride;
    const float* x1 = xsrc + (er4 + 1) * xstride;
    const float* x2 = xsrc + (er4 + 2) * xstride;
    const float* x3 = xsrc + (er4 + 3) * xstride;
#pragma unroll
    for (int kk = 0; kk < 32; kk++) {
        float a0 = x0[kk], a1 = x1[kk], a2 = x2[kk], a3 = x3[kk];
        float4 b0 = *(const float4*)(ws + kk * WS_STRIDE + oc8);
        float4 b1 = *(const float4*)(ws + kk * WS_STRIDE + oc8 + 4);
        float bb[8] = {b0.x, b0.y, b0.z, b0.w, b1.x, b1.y, b1.z, b1.w};
#pragma unroll
        for (int j = 0; j < 8; j++) {
            acc[0][j] = fmaf(a0, bb[j], acc[0][j]);
            acc[1][j] = fmaf(a1, bb[j], acc[1][j]);
            acc[2][j] = fmaf(a2, bb[j], acc[2][j]);
            acc[3][j] = fmaf(a3, bb[j], acc[3][j]);
        }
    }
}

// ============================================================================
// Kernel A: fused edge MLP (3 layers) + scatter-add of messages
// ============================================================================
__global__ __launch_bounds__(NTHREADS) void edge_kernel(
    const float* __restrict__ hV, const float* __restrict__ hE,
    const int* __restrict__ src, const int* __restrict__ dst,
    const float* __restrict__ W1, const float* __restrict__ b1,
    const float* __restrict__ W2, const float* __restrict__ b2,
    const float* __restrict__ W3, const float* __restrict__ b3)
{
    extern __shared__ float sm[];
    float* xs = sm;                         // [TE][XS_STRIDE]  (layer-1 input / layer-3 input reuse)
    float* ws = xs + TE * XS_STRIDE;        // [32][WS_STRIDE]
    float* ys = ws + 32 * WS_STRIDE;        // [TE][YS_STRIDE]
    __shared__ int sidx[TE];
    __shared__ int didx[TE];

    int tid = threadIdx.x;
    size_t e0 = (size_t)blockIdx.x * TE;

    if (tid < TE)            sidx[tid]      = src[e0 + tid];
    else if (tid < 2 * TE)   didx[tid - TE] = dst[e0 + (tid - TE)];
    __syncthreads();

    // Gather h_EV = [hV[src], hE, hV[dst]] into xs (float4 vectorized)
#pragma unroll
    for (int t = 0; t < 24; t++) {
        int idx = tid + t * NTHREADS;       // 0..6143 = TE * 96
        int e   = idx / 96;
        int c4  = idx % 96;
        const float* p;
        if (c4 < 32)       p = hV + (size_t)sidx[e] * HDIM + c4 * 4;
        else if (c4 < 64)  p = hE + (e0 + e) * HDIM + (c4 - 32) * 4;
        else               p = hV + (size_t)didx[e] * HDIM + (c4 - 64) * 4;
        *(float4*)(xs + e * XS_STRIDE + c4 * 4) = *(const float4*)p;
    }
    __syncthreads();

    int er4 = (tid >> 4) * 4;
    int oc8 = (tid & 15) * 8;
    float acc[4][8];

    // ---- layer 1: [E,384] @ W1^T -> gelu -> ys
#pragma unroll
    for (int j = 0; j < 8; j++) {
        float bv = b1[oc8 + j];
        acc[0][j] = bv; acc[1][j] = bv; acc[2][j] = bv; acc[3][j] = bv;
    }
    for (int k0 = 0; k0 < K1; k0 += 32) {
        load_wchunk(W1, K1, k0, ws, tid);
        __syncthreads();
        gemm_accum(xs + k0, XS_STRIDE, ws, acc, er4, oc8);
        __syncthreads();
    }
#pragma unroll
    for (int i = 0; i < 4; i++)
#pragma unroll
        for (int j = 0; j < 8; j++)
            ys[(er4 + i) * YS_STRIDE + oc8 + j] = gelu_exact(acc[i][j]);
    __syncthreads();

    // ---- layer 2: ys @ W2^T -> gelu -> xs (viewed [TE][YS_STRIDE])
#pragma unroll
    for (int j = 0; j < 8; j++) {
        float bv = b2[oc8 + j];
        acc[0][j] = bv; acc[1][j] = bv; acc[2][j] = bv; acc[3][j] = bv;
    }
    for (int k0 = 0; k0 < HDIM; k0 += 32) {
        load_wchunk(W2, HDIM, k0, ws, tid);
        __syncthreads();
        gemm_accum(ys + k0, YS_STRIDE, ws, acc, er4, oc8);
        __syncthreads();
    }
#pragma unroll
    for (int i = 0; i < 4; i++)
#pragma unroll
        for (int j = 0; j < 8; j++)
            xs[(er4 + i) * YS_STRIDE + oc8 + j] = gelu_exact(acc[i][j]);
    __syncthreads();

    // ---- layer 3: -> message (no activation) -> ys
#pragma unroll
    for (int j = 0; j < 8; j++) {
        float bv = b3[oc8 + j];
        acc[0][j] = bv; acc[1][j] = bv; acc[2][j] = bv; acc[3][j] = bv;
    }
    for (int k0 = 0; k0 < HDIM; k0 += 32) {
        load_wchunk(W3, HDIM, k0, ws, tid);
        __syncthreads();
        gemm_accum(xs + k0, YS_STRIDE, ws, acc, er4, oc8);
        __syncthreads();
    }
#pragma unroll
    for (int i = 0; i < 4; i++)
#pragma unroll
        for (int j = 0; j < 8; j++)
            ys[(er4 + i) * YS_STRIDE + oc8 + j] = acc[i][j];
    __syncthreads();

    // ---- scatter-add messages (coalesced atomics)
#pragma unroll
    for (int t = 0; t < 32; t++) {
        int idx = tid + t * NTHREADS;       // TE*128 = 8192
        int e = idx >> 7;
        int o = idx & 127;
        atomicAdd(&g_nsum[(size_t)sidx[e] * HDIM + o], ys[e * YS_STRIDE + o]);
    }
    if (tid < TE) atomicAdd(&g_cnt[sidx[tid]], 1.0f);
}

// ============================================================================
// Kernel B: scatter-mean finalize + residual + LN1 + FFN + residual + LN2
// ============================================================================
__global__ __launch_bounds__(NTHREADS) void node_kernel(
    const float* __restrict__ hV,
    const float* __restrict__ ln1g, const float* __restrict__ ln1b,
    const float* __restrict__ ln2g, const float* __restrict__ ln2b,
    const float* __restrict__ Win,  const float* __restrict__ bin,
    const float* __restrict__ Wout, const float* __restrict__ bout,
    float* __restrict__ out)
{
    extern __shared__ float sm[];
    float* hs = sm;                         // [TN][YS_STRIDE] post-LN1 activations
    float* ws = hs + TN * YS_STRIDE;        // [32][WS_STRIDE]
    float* yf = ws + 32 * WS_STRIDE;        // [TN][Y5_STRIDE] FFN hidden

    int tid = threadIdx.x;
    int n0 = blockIdx.x * TN;

    // residual pre-LN values  (TN*HDIM = 8192 elements -> 32 iterations of 256)
#pragma unroll
    for (int t = 0; t < 32; t++) {
        int idx = tid + t * NTHREADS;
        int n = idx >> 7, o = idx & 127;
        int gn = n0 + n;
        float v = 0.0f;
        if (gn < NNODES) {
            float c = fmaxf(g_cnt[gn], 1.0f);
            v = hV[(size_t)gn * HDIM + o] + g_nsum[(size_t)gn * HDIM + o] / (c * SCALE_F);
        }
        hs[n * YS_STRIDE + o] = v;
    }
    __syncthreads();

    // LN1 (4 lanes per node, quad shuffle reduction)
    {
        int n = tid >> 2, q = tid & 3;
        float s = 0.0f, ss = 0.0f;
#pragma unroll
        for (int jj = 0; jj < 32; jj++) {
            float v = hs[n * YS_STRIDE + q * 32 + jj];
            s += v; ss += v * v;
        }
#pragma unroll
        for (int m = 1; m < 4; m <<= 1) {
            s  += __shfl_xor_sync(0xffffffffu, s,  m);
            ss += __shfl_xor_sync(0xffffffffu, ss, m);
        }
        float mu   = s * (1.0f / 128.0f);
        float var  = ss * (1.0f / 128.0f) - mu * mu;
        float rstd = rsqrtf(var + LN_EPS);
#pragma unroll
        for (int jj = 0; jj < 32; jj++) {
            int o = q * 32 + jj;
            float v = hs[n * YS_STRIDE + o];
            hs[n * YS_STRIDE + o] = (v - mu) * rstd * ln1g[o] + ln1b[o];
        }
    }
    __syncthreads();

    int er4 = (tid >> 4) * 4;
    int oc8 = (tid & 15) * 8;

    // FFN layer 1: 128 -> 512 (4 column blocks of 128)
    for (int nb = 0; nb < 4; nb++) {
        float acc[4][8];
#pragma unroll
        for (int j = 0; j < 8; j++) {
            float bv = bin[nb * 128 + oc8 + j];
            acc[0][j] = bv; acc[1][j] = bv; acc[2][j] = bv; acc[3][j] = bv;
        }
        for (int k0 = 0; k0 < HDIM; k0 += 32) {
            load_wchunk(Win + (size_t)nb * 128 * HDIM, HDIM, k0, ws, tid);
            __syncthreads();
            gemm_accum(hs + k0, YS_STRIDE, ws, acc, er4, oc8);
            __syncthreads();
        }
#pragma unroll
        for (int i = 0; i < 4; i++)
#pragma unroll
            for (int j = 0; j < 8; j++)
                yf[(er4 + i) * Y5_STRIDE + nb * 128 + oc8 + j] = gelu_exact(acc[i][j]);
        __syncthreads();
    }

    // FFN layer 2: 512 -> 128
    float acc[4][8];
#pragma unroll
    for (int j = 0; j < 8; j++) {
        float bv = bout[oc8 + j];
        acc[0][j] = bv; acc[1][j] = bv; acc[2][j] = bv; acc[3][j] = bv;
    }
    for (int k0 = 0; k0 < FFDIM; k0 += 32) {
        load_wchunk(Wout, FFDIM, k0, ws, tid);
        __syncthreads();
        gemm_accum(yf + k0, Y5_STRIDE, ws, acc, er4, oc8);
        __syncthreads();
    }

    // z = FFN(x) + x, stored into reused smem
    float* zs = yf;                          // reuse as [TN][YS_STRIDE]
#pragma unroll
    for (int i = 0; i < 4; i++)
#pragma unroll
        for (int j = 0; j < 8; j++)
            zs[(er4 + i) * YS_STRIDE + oc8 + j] =
                acc[i][j] + hs[(er4 + i) * YS_STRIDE + oc8 + j];
    __syncthreads();

    // LN2 + write out
    {
        int n = tid >> 2, q = tid & 3;
        float s = 0.0f, ss = 0.0f;
#pragma unroll
        for (int jj = 0; jj < 32; jj++) {
            float v = zs[n * YS_STRIDE + q * 32 + jj];
            s += v; ss += v * v;
        }
#pragma unroll
        for (int m = 1; m < 4; m <<= 1) {
            s  += __shfl_xor_sync(0xffffffffu, s,  m);
            ss += __shfl_xor_sync(0xffffffffu, ss, m);
        }
        float mu   = s * (1.0f / 128.0f);
        float var  = ss * (1.0f / 128.0f) - mu * mu;
        float rstd = rsqrtf(var + LN_EPS);
        int gn = n0 + n;
        if (gn < NNODES) {
#pragma unroll
            for (int jj = 0; jj < 32; jj++) {
                int o = q * 32 + jj;
                float v = zs[n * YS_STRIDE + o];
                out[(size_t)gn * HDIM + o] = (v - mu) * rstd * ln2g[o] + ln2b[o];
            }
        }
    }
}

// ============================================================================
// Launch
// ============================================================================
extern "C" void kernel_launch(void* const* d_in, const int* in_sizes, int n_in,
                              void* d_out, int out_size)
{
    const float* hV   = (const float*)d_in[0];
    const float* hE   = (const float*)d_in[1];
    const int*   src  = (const int*)  d_in[2];
    // d_in[3] = batch_id (unused)
    const int*   dst  = (const int*)  d_in[4];
    const float* W1   = (const float*)d_in[5];
    const float* b1   = (const float*)d_in[6];
    const float* W2   = (const float*)d_in[7];
    const float* b2   = (const float*)d_in[8];
    const float* W3   = (const float*)d_in[9];
    const float* b3   = (const float*)d_in[10];
    const float* ln1g = (const float*)d_in[11];
    const float* ln1b = (const float*)d_in[12];
    const float* ln2g = (const float*)d_in[13];
    const float* ln2b = (const float*)d_in[14];
    const float* Win  = (const float*)d_in[15];
    const float* bin  = (const float*)d_in[16];
    const float* Wout = (const float*)d_in[17];
    const float* bout = (const float*)d_in[18];
    float* out = (float*)d_out;

    const int EDGE_SMEM = (TE * XS_STRIDE + 32 * WS_STRIDE + TE * YS_STRIDE) * 4;  // 150016 B
    const int NODE_SMEM = (TN * YS_STRIDE + 32 * WS_STRIDE + TN * Y5_STRIDE) * 4;  // 182784 B

    cudaFuncSetAttribute(edge_kernel, cudaFuncAttributeMaxDynamicSharedMemorySize, EDGE_SMEM);
    cudaFuncSetAttribute(node_kernel, cudaFuncAttributeMaxDynamicSharedMemorySize, NODE_SMEM);

    void* nsum_p = nullptr;
    void* cnt_p  = nullptr;
    cudaGetSymbolAddress(&nsum_p, g_nsum);
    cudaGetSymbolAddress(&cnt_p,  g_cnt);
    cudaMemsetAsync(nsum_p, 0, sizeof(float) * (size_t)NNODES * HDIM);
    cudaMemsetAsync(cnt_p,  0, sizeof(float) * NNODES);

    edge_kernel<<<EDGES / TE, NTHREADS, EDGE_SMEM>>>(hV, hE, src, dst, W1, b1, W2, b2, W3, b3);
    node_kernel<<<(NNODES + TN - 1) / TN, NTHREADS, NODE_SMEM>>>(
        hV, ln1g, ln1b, ln2g, ln2b, Win, bin, Wout, bout, out);
}

// round 7
// speedup vs baseline: 2.7969x; 2.7969x over previous
#include <cuda_runtime.h>
#include <cuda_bf16.h>
#include <math.h>
#include <stdint.h>
#include <string.h>

#define EDGES    800000
#define NNODES   50000
#define HDIM     128
#define K1       384
#define FFDIM    512
#define TEM      128
#define TN       64
#define NTHREADS 256
#define WS_STRIDE 132
#define YS_STRIDE 132
#define Y5_STRIDE 516
#define SCALE_F  30.0f
#define LN_EPS   1e-5f

// smem strides (bytes)
#define SA1 784     // X1: 384 bf16 + 8 pad   (784/4=196 ≡ 4 mod 32)
#define SA2 272     // X2/X3: 128 bf16 + 8 pad (272/4=68 ≡ 4 mod 32)
#define XA_BYTES  (128 * SA1)      // 100352
#define WB_BYTES  (128 * SA1)      // 100352 (layer1 worst case)
#define X3_OFF    (128 * SA2)      // X3 region inside XA after X2

__device__ float g_nsum[(size_t)NNODES * HDIM];
__device__ float g_cnt[NNODES];

__device__ __forceinline__ float gelu_exact(float x) {
    return 0.5f * x * (1.0f + erff(x * 0.70710678118654752440f));
}
__device__ __forceinline__ uint32_t smem_u32(const void* p) {
    uint32_t a;
    asm("{ .reg .u64 t; cvta.to.shared.u64 t, %1; cvt.u32.u64 %0, t; }" : "=r"(a) : "l"(p));
    return a;
}
__device__ __forceinline__ void ldsm4(uint32_t r[4], uint32_t addr) {
    asm volatile("ldmatrix.sync.aligned.m8n8.x4.shared.b16 {%0,%1,%2,%3}, [%4];"
                 : "=r"(r[0]), "=r"(r[1]), "=r"(r[2]), "=r"(r[3]) : "r"(addr));
}
__device__ __forceinline__ void mma_bf16(float c[4], const uint32_t a[4],
                                         uint32_t b0, uint32_t b1) {
    asm volatile("mma.sync.aligned.m16n8k16.row.col.f32.bf16.bf16.f32 "
                 "{%0,%1,%2,%3}, {%4,%5,%6,%7}, {%8,%9}, {%0,%1,%2,%3};"
                 : "+f"(c[0]), "+f"(c[1]), "+f"(c[2]), "+f"(c[3])
                 : "r"(a[0]), "r"(a[1]), "r"(a[2]), "r"(a[3]), "r"(b0), "r"(b1));
}

// pack 4 floats (k..k+3) to 4 bf16 = 8 bytes
__device__ __forceinline__ void st_bf16x4(char* dst, float4 v) {
    __nv_bfloat162 h0 = __floats2bfloat162_rn(v.x, v.y);
    __nv_bfloat162 h1 = __floats2bfloat162_rn(v.z, v.w);
    uint32_t u0, u1;
    memcpy(&u0, &h0, 4); memcpy(&u1, &h1, 4);
    *(uint2*)dst = make_uint2(u0, u1);
}

// warp-tile mma over K: acc[2 mtile][8 ntile][4]
template <int KTOT, int SA, int SW>
__device__ __forceinline__ void mma_layer(const char* A, const char* W,
                                          float acc[2][8][4], int wm, int wn, int lane) {
    int row_off = (lane & 7) + ((lane >> 3) & 1) * 8;
    int col_off = (lane >> 4) * 8;
#pragma unroll
    for (int k0 = 0; k0 < KTOT; k0 += 16) {
        uint32_t a[2][4];
#pragma unroll
        for (int mi = 0; mi < 2; mi++)
            ldsm4(a[mi], smem_u32(A + (wm * 32 + mi * 16 + row_off) * SA
                                     + (k0 + col_off) * 2));
        uint32_t b[4][4];
#pragma unroll
        for (int np = 0; np < 4; np++)
            ldsm4(b[np], smem_u32(W + (wn * 64 + np * 16 + row_off) * SW
                                     + (k0 + col_off) * 2));
#pragma unroll
        for (int mi = 0; mi < 2; mi++)
#pragma unroll
            for (int np = 0; np < 4; np++) {
                mma_bf16(acc[mi][2 * np],     a[mi], b[np][0], b[np][2]);
                mma_bf16(acc[mi][2 * np + 1], a[mi], b[np][1], b[np][3]);
            }
    }
}

__device__ __forceinline__ void init_bias(float acc[2][8][4], const float* sb,
                                          int wn, int q) {
#pragma unroll
    for (int ni = 0; ni < 8; ni++) {
        int c = wn * 64 + ni * 8 + q * 2;
        float v0 = sb[c], v1 = sb[c + 1];
#pragma unroll
        for (int mi = 0; mi < 2; mi++) {
            acc[mi][ni][0] = v0; acc[mi][ni][1] = v1;
            acc[mi][ni][2] = v0; acc[mi][ni][3] = v1;
        }
    }
}

// epilogue: gelu+bf16 store to X (stride SA2)
__device__ __forceinline__ void epi_gelu(char* X, float acc[2][8][4],
                                         int wm, int wn, int g, int q) {
#pragma unroll
    for (int mi = 0; mi < 2; mi++) {
        int r0 = wm * 32 + mi * 16 + g;
#pragma unroll
        for (int ni = 0; ni < 8; ni++) {
            int c = wn * 64 + ni * 8 + q * 2;
            __nv_bfloat162 h0 = __floats2bfloat162_rn(gelu_exact(acc[mi][ni][0]),
                                                      gelu_exact(acc[mi][ni][1]));
            __nv_bfloat162 h1 = __floats2bfloat162_rn(gelu_exact(acc[mi][ni][2]),
                                                      gelu_exact(acc[mi][ni][3]));
            uint32_t u0, u1;
            memcpy(&u0, &h0, 4); memcpy(&u1, &h1, 4);
            *(uint32_t*)(X + r0 * SA2 + c * 2) = u0;
            *(uint32_t*)(X + (r0 + 8) * SA2 + c * 2) = u1;
        }
    }
}

// ============================================================================
// Edge kernel: bf16 mma.sync 3-layer MLP + scatter
// ============================================================================
__global__ __launch_bounds__(NTHREADS, 1) void edge_kernel_mma(
    const float* __restrict__ hV, const float* __restrict__ hE,
    const int* __restrict__ src, const int* __restrict__ dst,
    const float* __restrict__ W1, const float* __restrict__ b1,
    const float* __restrict__ W2, const float* __restrict__ b2,
    const float* __restrict__ W3, const float* __restrict__ b3)
{
    extern __shared__ char smem[];
    char* XA = smem;                 // X1 (stride SA1); later X2 @0, X3 @X3_OFF (stride SA2)
    char* WB = smem + XA_BYTES;      // weights; later MS fp32 staging

    __shared__ int   sidx[TEM];
    __shared__ int   didx[TEM];
    __shared__ float s_b1[HDIM], s_b2[HDIM], s_b3[HDIM];

    int tid = threadIdx.x;
    int wid = tid >> 5;
    int lane = tid & 31;
    int wm = wid & 3, wn = wid >> 2;
    int g = lane >> 2, q = lane & 3;
    size_t e0 = (size_t)blockIdx.x * TEM;

    if (tid < TEM) {
        sidx[tid] = src[e0 + tid];
        s_b1[tid] = b1[tid]; s_b2[tid] = b2[tid]; s_b3[tid] = b3[tid];
    } else {
        didx[tid - TEM] = dst[e0 + (tid - TEM)];
    }
    __syncthreads();

    // ---- Gather X1 = [hV[src] | hE | hV[dst]] -> bf16 (128 x 384, stride SA1)
#pragma unroll 4
    for (int t = 0; t < 48; t++) {
        int idx = tid + t * NTHREADS;   // 128 edges * 96 float4
        int e   = idx / 96;
        int c4  = idx % 96;
        const float* p;
        if (c4 < 32)       p = hV + (size_t)sidx[e] * HDIM + c4 * 4;
        else if (c4 < 64)  p = hE + (e0 + e) * HDIM + (c4 - 32) * 4;
        else               p = hV + (size_t)didx[e] * HDIM + (c4 - 64) * 4;
        st_bf16x4(XA + e * SA1 + c4 * 8, *(const float4*)p);
    }
    // ---- W1 (128 x 384) -> bf16 (stride SA1)
#pragma unroll 4
    for (int t = 0; t < 48; t++) {
        int idx = tid + t * NTHREADS;
        int n = idx / 96, c4 = idx % 96;
        st_bf16x4(WB + n * SA1 + c4 * 8, *(const float4*)(W1 + (size_t)n * K1 + c4 * 4));
    }
    __syncthreads();

    float acc[2][8][4];

    // ---- Layer 1
    init_bias(acc, s_b1, wn, q);
    mma_layer<K1, SA1, SA1>(XA, WB, acc, wm, wn, lane);
    __syncthreads();                       // all warps done reading XA/WB
    epi_gelu(XA, acc, wm, wn, g, q);       // X2 @ XA, stride SA2
#pragma unroll 4
    for (int t = 0; t < 16; t++) {         // W2 (128 x 128)
        int idx = tid + t * NTHREADS;
        int n = idx >> 5, c4 = idx & 31;
        st_bf16x4(WB + n * SA2 + c4 * 8, *(const float4*)(W2 + (size_t)n * HDIM + c4 * 4));
    }
    __syncthreads();

    // ---- Layer 2
    init_bias(acc, s_b2, wn, q);
    mma_layer<HDIM, SA2, SA2>(XA, WB, acc, wm, wn, lane);
    epi_gelu(XA + X3_OFF, acc, wm, wn, g, q);   // X3 region (nobody reads yet)
    __syncthreads();                            // warps done reading X2/WB
#pragma unroll 4
    for (int t = 0; t < 16; t++) {              // W3
        int idx = tid + t * NTHREADS;
        int n = idx >> 5, c4 = idx & 31;
        st_bf16x4(WB + n * SA2 + c4 * 8, *(const float4*)(W3 + (size_t)n * HDIM + c4 * 4));
    }
    __syncthreads();

    // ---- Layer 3
    init_bias(acc, s_b3, wn, q);
    mma_layer<HDIM, SA2, SA2>(XA + X3_OFF, WB, acc, wm, wn, lane);
    __syncthreads();                            // all warps done reading X3/WB

    // ---- Stage messages fp32 into WB (stride 132 floats)
    float* MS = (float*)WB;
#pragma unroll
    for (int mi = 0; mi < 2; mi++) {
        int r0 = wm * 32 + mi * 16 + g;
#pragma unroll
        for (int ni = 0; ni < 8; ni++) {
            int c = wn * 64 + ni * 8 + q * 2;
            *(float2*)(MS + r0 * 132 + c)       = make_float2(acc[mi][ni][0], acc[mi][ni][1]);
            *(float2*)(MS + (r0 + 8) * 132 + c) = make_float2(acc[mi][ni][2], acc[mi][ni][3]);
        }
    }
    __syncthreads();

    // ---- Coalesced scatter-add
#pragma unroll 4
    for (int t = 0; t < 64; t++) {
        int idx = tid + t * NTHREADS;   // 128*128
        int e = idx >> 7;
        int o = idx & 127;
        atomicAdd(&g_nsum[(size_t)sidx[e] * HDIM + o], MS[e * 132 + o]);
    }
    if (tid < TEM) atomicAdd(&g_cnt[sidx[tid]], 1.0f);
}

// ============================================================================
// Node kernel (fp32 path, unchanged)
// ============================================================================
__device__ __forceinline__ void load_wchunk(const float* __restrict__ W, int ldw, int k0,
                                            float* ws, int tid) {
#pragma unroll
    for (int t = 0; t < 4; t++) {
        int idx = tid + t * NTHREADS;
        int r   = idx >> 3;
        int c4  = idx & 7;
        float4 v = *(const float4*)(W + (size_t)r * ldw + k0 + c4 * 4);
        int kl = c4 * 4;
        ws[(kl + 0) * WS_STRIDE + r] = v.x;
        ws[(kl + 1) * WS_STRIDE + r] = v.y;
        ws[(kl + 2) * WS_STRIDE + r] = v.z;
        ws[(kl + 3) * WS_STRIDE + r] = v.w;
    }
}

__device__ __forceinline__ void gemm_accum(const float* xsrc, int xstride, const float* ws,
                                           float acc[4][8], int er4, int oc8) {
    const float* x0 = xsrc + (er4 + 0) * xstride;
    const float* x1 = xsrc + (er4 + 1) * xstride;
    const float* x2 = xsrc + (er4 + 2) * xstride;
    const float* x3 = xsrc + (er4 + 3) * xstride;
#pragma unroll
    for (int kk = 0; kk < 32; kk++) {
        float a0 = x0[kk], a1 = x1[kk], a2 = x2[kk], a3 = x3[kk];
        float4 b0 = *(const float4*)(ws + kk * WS_STRIDE + oc8);
        float4 b1 = *(const float4*)(ws + kk * WS_STRIDE + oc8 + 4);
        float bb[8] = {b0.x, b0.y, b0.z, b0.w, b1.x, b1.y, b1.z, b1.w};
#pragma unroll
        for (int j = 0; j < 8; j++) {
            acc[0][j] = fmaf(a0, bb[j], acc[0][j]);
            acc[1][j] = fmaf(a1, bb[j], acc[1][j]);
            acc[2][j] = fmaf(a2, bb[j], acc[2][j]);
            acc[3][j] = fmaf(a3, bb[j], acc[3][j]);
        }
    }
}

__global__ __launch_bounds__(NTHREADS) void node_kernel(
    const float* __restrict__ hV,
    const float* __restrict__ ln1g, const float* __restrict__ ln1b,
    const float* __restrict__ ln2g, const float* __restrict__ ln2b,
    const float* __restrict__ Win,  const float* __restrict__ bin,
    const float* __restrict__ Wout, const float* __restrict__ bout,
    float* __restrict__ out)
{
    extern __shared__ float sm[];
    float* hs = sm;
    float* ws = hs + TN * YS_STRIDE;
    float* yf = ws + 32 * WS_STRIDE;

    int tid = threadIdx.x;
    int n0 = blockIdx.x * TN;

#pragma unroll
    for (int t = 0; t < 32; t++) {
        int idx = tid + t * NTHREADS;
        int n = idx >> 7, o = idx & 127;
        int gn = n0 + n;
        float v = 0.0f;
        if (gn < NNODES) {
            float c = fmaxf(g_cnt[gn], 1.0f);
            v = hV[(size_t)gn * HDIM + o] + g_nsum[(size_t)gn * HDIM + o] / (c * SCALE_F);
        }
        hs[n * YS_STRIDE + o] = v;
    }
    __syncthreads();

    {
        int n = tid >> 2, q = tid & 3;
        float s = 0.0f, ss = 0.0f;
#pragma unroll
        for (int jj = 0; jj < 32; jj++) {
            float v = hs[n * YS_STRIDE + q * 32 + jj];
            s += v; ss += v * v;
        }
#pragma unroll
        for (int m = 1; m < 4; m <<= 1) {
            s  += __shfl_xor_sync(0xffffffffu, s,  m);
            ss += __shfl_xor_sync(0xffffffffu, ss, m);
        }
        float mu   = s * (1.0f / 128.0f);
        float var  = ss * (1.0f / 128.0f) - mu * mu;
        float rstd = rsqrtf(var + LN_EPS);
#pragma unroll
        for (int jj = 0; jj < 32; jj++) {
            int o = q * 32 + jj;
            float v = hs[n * YS_STRIDE + o];
            hs[n * YS_STRIDE + o] = (v - mu) * rstd * ln1g[o] + ln1b[o];
        }
    }
    __syncthreads();

    int er4 = (tid >> 4) * 4;
    int oc8 = (tid & 15) * 8;

    for (int nb = 0; nb < 4; nb++) {
        float acc[4][8];
#pragma unroll
        for (int j = 0; j < 8; j++) {
            float bv = bin[nb * 128 + oc8 + j];
            acc[0][j] = bv; acc[1][j] = bv; acc[2][j] = bv; acc[3][j] = bv;
        }
        for (int k0 = 0; k0 < HDIM; k0 += 32) {
            load_wchunk(Win + (size_t)nb * 128 * HDIM, HDIM, k0, ws, tid);
            __syncthreads();
            gemm_accum(hs + k0, YS_STRIDE, ws, acc, er4, oc8);
            __syncthreads();
        }
#pragma unroll
        for (int i = 0; i < 4; i++)
#pragma unroll
            for (int j = 0; j < 8; j++)
                yf[(er4 + i) * Y5_STRIDE + nb * 128 + oc8 + j] = gelu_exact(acc[i][j]);
        __syncthreads();
    }

    float acc[4][8];
#pragma unroll
    for (int j = 0; j < 8; j++) {
        float bv = bout[oc8 + j];
        acc[0][j] = bv; acc[1][j] = bv; acc[2][j] = bv; acc[3][j] = bv;
    }
    for (int k0 = 0; k0 < FFDIM; k0 += 32) {
        load_wchunk(Wout, FFDIM, k0, ws, tid);
        __syncthreads();
        gemm_accum(yf + k0, Y5_STRIDE, ws, acc, er4, oc8);
        __syncthreads();
    }

    float* zs = yf;
#pragma unroll
    for (int i = 0; i < 4; i++)
#pragma unroll
        for (int j = 0; j < 8; j++)
            zs[(er4 + i) * YS_STRIDE + oc8 + j] =
                acc[i][j] + hs[(er4 + i) * YS_STRIDE + oc8 + j];
    __syncthreads();

    {
        int n = tid >> 2, q = tid & 3;
        float s = 0.0f, ss = 0.0f;
#pragma unroll
        for (int jj = 0; jj < 32; jj++) {
            float v = zs[n * YS_STRIDE + q * 32 + jj];
            s += v; ss += v * v;
        }
#pragma unroll
        for (int m = 1; m < 4; m <<= 1) {
            s  += __shfl_xor_sync(0xffffffffu, s,  m);
            ss += __shfl_xor_sync(0xffffffffu, ss, m);
        }
        float mu   = s * (1.0f / 128.0f);
        float var  = ss * (1.0f / 128.0f) - mu * mu;
        float rstd = rsqrtf(var + LN_EPS);
        int gn = n0 + n;
        if (gn < NNODES) {
#pragma unroll
            for (int jj = 0; jj < 32; jj++) {
                int o = q * 32 + jj;
                float v = zs[n * YS_STRIDE + o];
                out[(size_t)gn * HDIM + o] = (v - mu) * rstd * ln2g[o] + ln2b[o];
            }
        }
    }
}

// ============================================================================
// Launch
// ============================================================================
extern "C" void kernel_launch(void* const* d_in, const int* in_sizes, int n_in,
                              void* d_out, int out_size)
{
    const float* hV   = (const float*)d_in[0];
    const float* hE   = (const float*)d_in[1];
    const int*   src  = (const int*)  d_in[2];
    const int*   dst  = (const int*)  d_in[4];
    const float* W1   = (const float*)d_in[5];
    const float* b1   = (const float*)d_in[6];
    const float* W2   = (const float*)d_in[7];
    const float* b2   = (const float*)d_in[8];
    const float* W3   = (const float*)d_in[9];
    const float* b3   = (const float*)d_in[10];
    const float* ln1g = (const float*)d_in[11];
    const float* ln1b = (const float*)d_in[12];
    const float* ln2g = (const float*)d_in[13];
    const float* ln2b = (const float*)d_in[14];
    const float* Win  = (const float*)d_in[15];
    const float* bin  = (const float*)d_in[16];
    const float* Wout = (const float*)d_in[17];
    const float* bout = (const float*)d_in[18];
    float* out = (float*)d_out;

    const int EDGE_SMEM = XA_BYTES + WB_BYTES;   // 200704
    const int NODE_SMEM = (TN * YS_STRIDE + 32 * WS_STRIDE + TN * Y5_STRIDE) * 4;

    cudaFuncSetAttribute(edge_kernel_mma, cudaFuncAttributeMaxDynamicSharedMemorySize, EDGE_SMEM);
    cudaFuncSetAttribute(node_kernel, cudaFuncAttributeMaxDynamicSharedMemorySize, NODE_SMEM);

    void* nsum_p = nullptr;
    void* cnt_p  = nullptr;
    cudaGetSymbolAddress(&nsum_p, g_nsum);
    cudaGetSymbolAddress(&cnt_p,  g_cnt);
    cudaMemsetAsync(nsum_p, 0, sizeof(float) * (size_t)NNODES * HDIM);
    cudaMemsetAsync(cnt_p,  0, sizeof(float) * NNODES);

    edge_kernel_mma<<<EDGES / TEM, NTHREADS, EDGE_SMEM>>>(hV, hE, src, dst,
                                                          W1, b1, W2, b2, W3, b3);
    node_kernel<<<(NNODES + TN - 1) / TN, NTHREADS, NODE_SMEM>>>(
        hV, ln1g, ln1b, ln2g, ln2b, Win, bin, Wout, bout, out);
}

// round 8
// speedup vs baseline: 3.6515x; 1.3055x over previous
#include <cuda_runtime.h>
#include <cuda_bf16.h>
#include <math.h>
#include <stdint.h>
#include <string.h>

#define EDGES    800000
#define NNODES   50000
#define HDIM     128
#define K1       384
#define FFDIM    512
#define TEM      128
#define TNN      128          // nodes per CTA (node kernel)
#define NTHREADS 256
#define SCALE_F  30.0f
#define LN_EPS   1e-5f

// smem strides (bytes)
#define SA1 784     // X1: 384 bf16 + 8 pad
#define SA2 272     // 128 bf16 + 8 pad
#define XA_BYTES  (128 * SA1)      // 100352
#define WB_BYTES  (128 * SA1)
#define X3_OFF    (128 * SA2)

// node kernel smem layout (bytes)
#define HS_STRIDE 132                      // floats
#define HS_BYTES  (TNN * HS_STRIDE * 4)    // 67584
#define NX_OFF    HS_BYTES                 // X bf16 [128][SA2]
#define NH_OFF    (NX_OFF + 128 * SA2)     // Hb bf16 [128][SA2]
#define NW_OFF    (NH_OFF + 128 * SA2)     // Wb bf16 [128][SA2]
#define NODE_SMEM (NW_OFF + 128 * SA2)     // 172032

__device__ float g_nsum[(size_t)NNODES * HDIM];
__device__ float g_cnt[NNODES];

__device__ __forceinline__ float gelu_exact(float x) {
    return 0.5f * x * (1.0f + erff(x * 0.70710678118654752440f));
}
__device__ __forceinline__ uint32_t smem_u32(const void* p) {
    uint32_t a;
    asm("{ .reg .u64 t; cvta.to.shared.u64 t, %1; cvt.u32.u64 %0, t; }" : "=r"(a) : "l"(p));
    return a;
}
__device__ __forceinline__ void ldsm4(uint32_t r[4], uint32_t addr) {
    asm volatile("ldmatrix.sync.aligned.m8n8.x4.shared.b16 {%0,%1,%2,%3}, [%4];"
                 : "=r"(r[0]), "=r"(r[1]), "=r"(r[2]), "=r"(r[3]) : "r"(addr));
}
__device__ __forceinline__ void mma_bf16(float c[4], const uint32_t a[4],
                                         uint32_t b0, uint32_t b1) {
    asm volatile("mma.sync.aligned.m16n8k16.row.col.f32.bf16.bf16.f32 "
                 "{%0,%1,%2,%3}, {%4,%5,%6,%7}, {%8,%9}, {%0,%1,%2,%3};"
                 : "+f"(c[0]), "+f"(c[1]), "+f"(c[2]), "+f"(c[3])
                 : "r"(a[0]), "r"(a[1]), "r"(a[2]), "r"(a[3]), "r"(b0), "r"(b1));
}
__device__ __forceinline__ void st_bf16x4(char* dst, float4 v) {
    __nv_bfloat162 h0 = __floats2bfloat162_rn(v.x, v.y);
    __nv_bfloat162 h1 = __floats2bfloat162_rn(v.z, v.w);
    uint32_t u0, u1;
    memcpy(&u0, &h0, 4); memcpy(&u1, &h1, 4);
    *(uint2*)dst = make_uint2(u0, u1);
}

template <int KTOT, int SA, int SW>
__device__ __forceinline__ void mma_layer(const char* A, const char* W,
                                          float acc[2][8][4], int wm, int wn, int lane) {
    int row_off = (lane & 7) + ((lane >> 3) & 1) * 8;
    int col_off = (lane >> 4) * 8;
#pragma unroll
    for (int k0 = 0; k0 < KTOT; k0 += 16) {
        uint32_t a[2][4];
#pragma unroll
        for (int mi = 0; mi < 2; mi++)
            ldsm4(a[mi], smem_u32(A + (wm * 32 + mi * 16 + row_off) * SA
                                     + (k0 + col_off) * 2));
        uint32_t b[4][4];
#pragma unroll
        for (int np = 0; np < 4; np++)
            ldsm4(b[np], smem_u32(W + (wn * 64 + np * 16 + row_off) * SW
                                     + (k0 + col_off) * 2));
#pragma unroll
        for (int mi = 0; mi < 2; mi++)
#pragma unroll
            for (int np = 0; np < 4; np++) {
                mma_bf16(acc[mi][2 * np],     a[mi], b[np][0], b[np][2]);
                mma_bf16(acc[mi][2 * np + 1], a[mi], b[np][1], b[np][3]);
            }
    }
}

__device__ __forceinline__ void init_bias(float acc[2][8][4], const float* sb,
                                          int wn, int q) {
#pragma unroll
    for (int ni = 0; ni < 8; ni++) {
        int c = wn * 64 + ni * 8 + q * 2;
        float v0 = sb[c], v1 = sb[c + 1];
#pragma unroll
        for (int mi = 0; mi < 2; mi++) {
            acc[mi][ni][0] = v0; acc[mi][ni][1] = v1;
            acc[mi][ni][2] = v0; acc[mi][ni][3] = v1;
        }
    }
}

__device__ __forceinline__ void epi_gelu(char* X, float acc[2][8][4],
                                         int wm, int wn, int g, int q) {
#pragma unroll
    for (int mi = 0; mi < 2; mi++) {
        int r0 = wm * 32 + mi * 16 + g;
#pragma unroll
        for (int ni = 0; ni < 8; ni++) {
            int c = wn * 64 + ni * 8 + q * 2;
            __nv_bfloat162 h0 = __floats2bfloat162_rn(gelu_exact(acc[mi][ni][0]),
                                                      gelu_exact(acc[mi][ni][1]));
            __nv_bfloat162 h1 = __floats2bfloat162_rn(gelu_exact(acc[mi][ni][2]),
                                                      gelu_exact(acc[mi][ni][3]));
            uint32_t u0, u1;
            memcpy(&u0, &h0, 4); memcpy(&u1, &h1, 4);
            *(uint32_t*)(X + r0 * SA2 + c * 2) = u0;
            *(uint32_t*)(X + (r0 + 8) * SA2 + c * 2) = u1;
        }
    }
}

// ============================================================================
// Edge kernel: bf16 mma.sync 3-layer MLP + scatter (unchanged from R7)
// ============================================================================
__global__ __launch_bounds__(NTHREADS, 1) void edge_kernel_mma(
    const float* __restrict__ hV, const float* __restrict__ hE,
    const int* __restrict__ src, const int* __restrict__ dst,
    const float* __restrict__ W1, const float* __restrict__ b1,
    const float* __restrict__ W2, const float* __restrict__ b2,
    const float* __restrict__ W3, const float* __restrict__ b3)
{
    extern __shared__ char smem[];
    char* XA = smem;
    char* WB = smem + XA_BYTES;

    __shared__ int   sidx[TEM];
    __shared__ int   didx[TEM];
    __shared__ float s_b1[HDIM], s_b2[HDIM], s_b3[HDIM];

    int tid = threadIdx.x;
    int wid = tid >> 5;
    int lane = tid & 31;
    int wm = wid & 3, wn = wid >> 2;
    int g = lane >> 2, q = lane & 3;
    size_t e0 = (size_t)blockIdx.x * TEM;

    if (tid < TEM) {
        sidx[tid] = src[e0 + tid];
        s_b1[tid] = b1[tid]; s_b2[tid] = b2[tid]; s_b3[tid] = b3[tid];
    } else {
        didx[tid - TEM] = dst[e0 + (tid - TEM)];
    }
    __syncthreads();

#pragma unroll 4
    for (int t = 0; t < 48; t++) {
        int idx = tid + t * NTHREADS;
        int e   = idx / 96;
        int c4  = idx % 96;
        const float* p;
        if (c4 < 32)       p = hV + (size_t)sidx[e] * HDIM + c4 * 4;
        else if (c4 < 64)  p = hE + (e0 + e) * HDIM + (c4 - 32) * 4;
        else               p = hV + (size_t)didx[e] * HDIM + (c4 - 64) * 4;
        st_bf16x4(XA + e * SA1 + c4 * 8, *(const float4*)p);
    }
#pragma unroll 4
    for (int t = 0; t < 48; t++) {
        int idx = tid + t * NTHREADS;
        int n = idx / 96, c4 = idx % 96;
        st_bf16x4(WB + n * SA1 + c4 * 8, *(const float4*)(W1 + (size_t)n * K1 + c4 * 4));
    }
    __syncthreads();

    float acc[2][8][4];

    init_bias(acc, s_b1, wn, q);
    mma_layer<K1, SA1, SA1>(XA, WB, acc, wm, wn, lane);
    __syncthreads();
    epi_gelu(XA, acc, wm, wn, g, q);
#pragma unroll 4
    for (int t = 0; t < 16; t++) {
        int idx = tid + t * NTHREADS;
        int n = idx >> 5, c4 = idx & 31;
        st_bf16x4(WB + n * SA2 + c4 * 8, *(const float4*)(W2 + (size_t)n * HDIM + c4 * 4));
    }
    __syncthreads();

    init_bias(acc, s_b2, wn, q);
    mma_layer<HDIM, SA2, SA2>(XA, WB, acc, wm, wn, lane);
    epi_gelu(XA + X3_OFF, acc, wm, wn, g, q);
    __syncthreads();
#pragma unroll 4
    for (int t = 0; t < 16; t++) {
        int idx = tid + t * NTHREADS;
        int n = idx >> 5, c4 = idx & 31;
        st_bf16x4(WB + n * SA2 + c4 * 8, *(const float4*)(W3 + (size_t)n * HDIM + c4 * 4));
    }
    __syncthreads();

    init_bias(acc, s_b3, wn, q);
    mma_layer<HDIM, SA2, SA2>(XA + X3_OFF, WB, acc, wm, wn, lane);
    __syncthreads();

    float* MS = (float*)WB;
#pragma unroll
    for (int mi = 0; mi < 2; mi++) {
        int r0 = wm * 32 + mi * 16 + g;
#pragma unroll
        for (int ni = 0; ni < 8; ni++) {
            int c = wn * 64 + ni * 8 + q * 2;
            *(float2*)(MS + r0 * 132 + c)       = make_float2(acc[mi][ni][0], acc[mi][ni][1]);
            *(float2*)(MS + (r0 + 8) * 132 + c) = make_float2(acc[mi][ni][2], acc[mi][ni][3]);
        }
    }
    __syncthreads();

#pragma unroll 4
    for (int t = 0; t < 64; t++) {
        int idx = tid + t * NTHREADS;
        int e = idx >> 7;
        int o = idx & 127;
        atomicAdd(&g_nsum[(size_t)sidx[e] * HDIM + o], MS[e * 132 + o]);
    }
    if (tid < TEM) atomicAdd(&g_cnt[sidx[tid]], 1.0f);
}

// ============================================================================
// Node kernel: bf16 mma.sync FFN + fp32 LN / residuals
// ============================================================================
__global__ __launch_bounds__(NTHREADS, 1) void node_kernel_mma(
    const float* __restrict__ hV,
    const float* __restrict__ ln1g, const float* __restrict__ ln1b,
    const float* __restrict__ ln2g, const float* __restrict__ ln2b,
    const float* __restrict__ Win,  const float* __restrict__ bin,
    const float* __restrict__ Wout, const float* __restrict__ bout,
    float* __restrict__ out)
{
    extern __shared__ char smem[];
    float* hs = (float*)smem;            // [TNN][HS_STRIDE] fp32 post-LN1 (residual)
    char*  X  = smem + NX_OFF;           // bf16 [128][SA2] FFN input
    char*  Hb = smem + NH_OFF;           // bf16 [128][SA2] hidden block
    char*  Wb = smem + NW_OFF;           // bf16 [128][SA2] weight block

    __shared__ float s_bout[HDIM];

    int tid = threadIdx.x;
    int wid = tid >> 5;
    int lane = tid & 31;
    int wm = wid & 3, wn = wid >> 2;
    int g = lane >> 2, q = lane & 3;
    int n0 = blockIdx.x * TNN;

    if (tid < HDIM) s_bout[tid] = bout[tid];

    // ---- residual: x = hV + mean(msg)/SCALE  (fp32)
#pragma unroll 4
    for (int t = 0; t < 64; t++) {
        int idx = tid + t * NTHREADS;    // 128*128
        int n = idx >> 7, o = idx & 127;
        int gn = n0 + n;
        float v = 0.0f;
        if (gn < NNODES) {
            float c = fmaxf(g_cnt[gn], 1.0f);
            v = hV[(size_t)gn * HDIM + o] + g_nsum[(size_t)gn * HDIM + o] / (c * SCALE_F);
        }
        hs[n * HS_STRIDE + o] = v;
    }
    __syncthreads();

    // ---- LN1: 2 lanes per row; write fp32 hs + bf16 X
    {
        int n = tid >> 1, h = tid & 1;
        float s = 0.0f, ss = 0.0f;
#pragma unroll
        for (int jj = 0; jj < 64; jj++) {
            float v = hs[n * HS_STRIDE + h * 64 + jj];
            s += v; ss += v * v;
        }
        s  += __shfl_xor_sync(0xffffffffu, s,  1);
        ss += __shfl_xor_sync(0xffffffffu, ss, 1);
        float mu   = s * (1.0f / 128.0f);
        float var  = ss * (1.0f / 128.0f) - mu * mu;
        float rstd = rsqrtf(var + LN_EPS);
#pragma unroll
        for (int jj = 0; jj < 64; jj += 2) {
            int o = h * 64 + jj;
            float v0 = (hs[n * HS_STRIDE + o]     - mu) * rstd * ln1g[o]     + ln1b[o];
            float v1 = (hs[n * HS_STRIDE + o + 1] - mu) * rstd * ln1g[o + 1] + ln1b[o + 1];
            hs[n * HS_STRIDE + o]     = v0;
            hs[n * HS_STRIDE + o + 1] = v1;
            __nv_bfloat162 hh = __floats2bfloat162_rn(v0, v1);
            uint32_t u; memcpy(&u, &hh, 4);
            *(uint32_t*)(X + n * SA2 + o * 2) = u;
        }
    }

    // ---- FFN: dh accumulates in registers across 4 K-blocks
    float dh[2][8][4];
    init_bias(dh, s_bout, wn, q);

    for (int nb = 0; nb < 4; nb++) {
        __syncthreads();    // Wb free (prev mma done) + X ready (nb=0)
        // load Win block [128 rows of nb*128..][K=128] -> Wb
#pragma unroll 4
        for (int t = 0; t < 16; t++) {
            int idx = tid + t * NTHREADS;
            int n = idx >> 5, c4 = idx & 31;
            st_bf16x4(Wb + n * SA2 + c4 * 8,
                      *(const float4*)(Win + (size_t)(nb * 128 + n) * HDIM + c4 * 4));
        }
        __syncthreads();

        float acc[2][8][4];
        init_bias(acc, bin + nb * 128, wn, q);
        mma_layer<HDIM, SA2, SA2>(X, Wb, acc, wm, wn, lane);
        __syncthreads();    // all warps done reading Wb
        epi_gelu(Hb, acc, wm, wn, g, q);

        // load Wout K-slice [128 rows][k = nb*128..] -> Wb
#pragma unroll 4
        for (int t = 0; t < 16; t++) {
            int idx = tid + t * NTHREADS;
            int n = idx >> 5, c4 = idx & 31;
            st_bf16x4(Wb + n * SA2 + c4 * 8,
                      *(const float4*)(Wout + (size_t)n * FFDIM + nb * 128 + c4 * 4));
        }
        __syncthreads();    // Hb + Wb ready

        mma_layer<HDIM, SA2, SA2>(Hb, Wb, dh, wm, wn, lane);
    }
    __syncthreads();

    // ---- z = dh + hs -> zs (reuse X/Hb region as fp32 [128][132])
    float* zs = (float*)X;
#pragma unroll
    for (int mi = 0; mi < 2; mi++) {
        int r0 = wm * 32 + mi * 16 + g;
#pragma unroll
        for (int ni = 0; ni < 8; ni++) {
            int c = wn * 64 + ni * 8 + q * 2;
            zs[r0 * 132 + c]           = dh[mi][ni][0] + hs[r0 * HS_STRIDE + c];
            zs[r0 * 132 + c + 1]       = dh[mi][ni][1] + hs[r0 * HS_STRIDE + c + 1];
            zs[(r0 + 8) * 132 + c]     = dh[mi][ni][2] + hs[(r0 + 8) * HS_STRIDE + c];
            zs[(r0 + 8) * 132 + c + 1] = dh[mi][ni][3] + hs[(r0 + 8) * HS_STRIDE + c + 1];
        }
    }
    __syncthreads();

    // ---- LN2 + store
    {
        int n = tid >> 1, h = tid & 1;
        float s = 0.0f, ss = 0.0f;
#pragma unroll
        for (int jj = 0; jj < 64; jj++) {
            float v = zs[n * 132 + h * 64 + jj];
            s += v; ss += v * v;
        }
        s  += __shfl_xor_sync(0xffffffffu, s,  1);
        ss += __shfl_xor_sync(0xffffffffu, ss, 1);
        float mu   = s * (1.0f / 128.0f);
        float var  = ss * (1.0f / 128.0f) - mu * mu;
        float rstd = rsqrtf(var + LN_EPS);
        int gn = n0 + n;
        if (gn < NNODES) {
#pragma unroll
            for (int jj = 0; jj < 64; jj++) {
                int o = h * 64 + jj;
                float v = zs[n * 132 + o];
                out[(size_t)gn * HDIM + o] = (v - mu) * rstd * ln2g[o] + ln2b[o];
            }
        }
    }
}

// ============================================================================
// Launch
// ============================================================================
extern "C" void kernel_launch(void* const* d_in, const int* in_sizes, int n_in,
                              void* d_out, int out_size)
{
    const float* hV   = (const float*)d_in[0];
    const float* hE   = (const float*)d_in[1];
    const int*   src  = (const int*)  d_in[2];
    const int*   dst  = (const int*)  d_in[4];
    const float* W1   = (const float*)d_in[5];
    const float* b1   = (const float*)d_in[6];
    const float* W2   = (const float*)d_in[7];
    const float* b2   = (const float*)d_in[8];
    const float* W3   = (const float*)d_in[9];
    const float* b3   = (const float*)d_in[10];
    const float* ln1g = (const float*)d_in[11];
    const float* ln1b = (const float*)d_in[12];
    const float* ln2g = (const float*)d_in[13];
    const float* ln2b = (const float*)d_in[14];
    const float* Win  = (const float*)d_in[15];
    const float* bin  = (const float*)d_in[16];
    const float* Wout = (const float*)d_in[17];
    const float* bout = (const float*)d_in[18];
    float* out = (float*)d_out;

    const int EDGE_SMEM = XA_BYTES + WB_BYTES;   // 200704

    cudaFuncSetAttribute(edge_kernel_mma, cudaFuncAttributeMaxDynamicSharedMemorySize, EDGE_SMEM);
    cudaFuncSetAttribute(node_kernel_mma, cudaFuncAttributeMaxDynamicSharedMemorySize, NODE_SMEM);

    void* nsum_p = nullptr;
    void* cnt_p  = nullptr;
    cudaGetSymbolAddress(&nsum_p, g_nsum);
    cudaGetSymbolAddress(&cnt_p,  g_cnt);
    cudaMemsetAsync(nsum_p, 0, sizeof(float) * (size_t)NNODES * HDIM);
    cudaMemsetAsync(cnt_p,  0, sizeof(float) * NNODES);

    edge_kernel_mma<<<EDGES / TEM, NTHREADS, EDGE_SMEM>>>(hV, hE, src, dst,
                                                          W1, b1, W2, b2, W3, b3);
    node_kernel_mma<<<(NNODES + TNN - 1) / TNN, NTHREADS, NODE_SMEM>>>(
        hV, ln1g, ln1b, ln2g, ln2b, Win, bin, Wout, bout, out);
}

// round 9
// speedup vs baseline: 3.8870x; 1.0645x over previous
#include <cuda_runtime.h>
#include <cuda_bf16.h>
#include <math.h>
#include <stdint.h>
#include <string.h>

#define EDGES    800000
#define NNODES   50000
#define HDIM     128
#define K1       384
#define FFDIM    512
#define TEM2     64            // edges per tile (persistent edge kernel)
#define NTILES   (EDGES / TEM2)
#define GRID_E   148
#define TNN      128           // nodes per CTA (node kernel)
#define NTHREADS 256
#define SCALE_F  30.0f
#define LN_EPS   1e-5f

// smem strides (bytes)
#define SA1 784     // 384 bf16 + pad
#define SA2 272     // 128 bf16 + pad

// edge kernel smem layout (bytes)
#define EW1_OFF  0
#define EW2_OFF  (128 * SA1)               // 100352
#define EW3_OFF  (EW2_OFF + 128 * SA2)     // 135168
#define EX_OFF   (EW3_OFF + 128 * SA2)     // 169984
#define EX3_OFF  (64 * SA2)                // X3 offset inside X region
#define EDGE_SMEM (EX_OFF + 64 * SA1)      // 220160

// node kernel smem layout (bytes)
#define HS_STRIDE 132
#define HS_BYTES  (TNN * HS_STRIDE * 4)
#define NX_OFF    HS_BYTES
#define NH_OFF    (NX_OFF + 128 * SA2)
#define NW_OFF    (NH_OFF + 128 * SA2)
#define NODE_SMEM (NW_OFF + 128 * SA2)

__device__ float g_nsum[(size_t)NNODES * HDIM];
__device__ float g_cnt[NNODES];

__device__ __forceinline__ float gelu_exact(float x) {
    return 0.5f * x * (1.0f + erff(x * 0.70710678118654752440f));
}
__device__ __forceinline__ uint32_t smem_u32(const void* p) {
    uint32_t a;
    asm("{ .reg .u64 t; cvta.to.shared.u64 t, %1; cvt.u32.u64 %0, t; }" : "=r"(a) : "l"(p));
    return a;
}
__device__ __forceinline__ void ldsm4(uint32_t r[4], uint32_t addr) {
    asm volatile("ldmatrix.sync.aligned.m8n8.x4.shared.b16 {%0,%1,%2,%3}, [%4];"
                 : "=r"(r[0]), "=r"(r[1]), "=r"(r[2]), "=r"(r[3]) : "r"(addr));
}
__device__ __forceinline__ void mma_bf16(float c[4], const uint32_t a[4],
                                         uint32_t b0, uint32_t b1) {
    asm volatile("mma.sync.aligned.m16n8k16.row.col.f32.bf16.bf16.f32 "
                 "{%0,%1,%2,%3}, {%4,%5,%6,%7}, {%8,%9}, {%0,%1,%2,%3};"
                 : "+f"(c[0]), "+f"(c[1]), "+f"(c[2]), "+f"(c[3])
                 : "r"(a[0]), "r"(a[1]), "r"(a[2]), "r"(a[3]), "r"(b0), "r"(b1));
}
__device__ __forceinline__ void st_bf16x4(char* dst, float4 v) {
    __nv_bfloat162 h0 = __floats2bfloat162_rn(v.x, v.y);
    __nv_bfloat162 h1 = __floats2bfloat162_rn(v.z, v.w);
    uint32_t u0, u1;
    memcpy(&u0, &h0, 4); memcpy(&u1, &h1, 4);
    *(uint2*)dst = make_uint2(u0, u1);
}

// ---------------- 32x64 warp-tile (node kernel, 8 warps = 4M x 2N) ----------
template <int KTOT, int SA, int SW>
__device__ __forceinline__ void mma_layer(const char* A, const char* W,
                                          float acc[2][8][4], int wm, int wn, int lane) {
    int row_off = (lane & 7) + ((lane >> 3) & 1) * 8;
    int col_off = (lane >> 4) * 8;
#pragma unroll
    for (int k0 = 0; k0 < KTOT; k0 += 16) {
        uint32_t a[2][4];
#pragma unroll
        for (int mi = 0; mi < 2; mi++)
            ldsm4(a[mi], smem_u32(A + (wm * 32 + mi * 16 + row_off) * SA
                                     + (k0 + col_off) * 2));
        uint32_t b[4][4];
#pragma unroll
        for (int np = 0; np < 4; np++)
            ldsm4(b[np], smem_u32(W + (wn * 64 + np * 16 + row_off) * SW
                                     + (k0 + col_off) * 2));
#pragma unroll
        for (int mi = 0; mi < 2; mi++)
#pragma unroll
            for (int np = 0; np < 4; np++) {
                mma_bf16(acc[mi][2 * np],     a[mi], b[np][0], b[np][2]);
                mma_bf16(acc[mi][2 * np + 1], a[mi], b[np][1], b[np][3]);
            }
    }
}
__device__ __forceinline__ void init_bias(float acc[2][8][4], const float* sb,
                                          int wn, int q) {
#pragma unroll
    for (int ni = 0; ni < 8; ni++) {
        int c = wn * 64 + ni * 8 + q * 2;
        float v0 = sb[c], v1 = sb[c + 1];
#pragma unroll
        for (int mi = 0; mi < 2; mi++) {
            acc[mi][ni][0] = v0; acc[mi][ni][1] = v1;
            acc[mi][ni][2] = v0; acc[mi][ni][3] = v1;
        }
    }
}
__device__ __forceinline__ void epi_gelu(char* X, float acc[2][8][4],
                                         int wm, int wn, int g, int q) {
#pragma unroll
    for (int mi = 0; mi < 2; mi++) {
        int r0 = wm * 32 + mi * 16 + g;
#pragma unroll
        for (int ni = 0; ni < 8; ni++) {
            int c = wn * 64 + ni * 8 + q * 2;
            __nv_bfloat162 h0 = __floats2bfloat162_rn(gelu_exact(acc[mi][ni][0]),
                                                      gelu_exact(acc[mi][ni][1]));
            __nv_bfloat162 h1 = __floats2bfloat162_rn(gelu_exact(acc[mi][ni][2]),
                                                      gelu_exact(acc[mi][ni][3]));
            uint32_t u0, u1;
            memcpy(&u0, &h0, 4); memcpy(&u1, &h1, 4);
            *(uint32_t*)(X + r0 * SA2 + c * 2) = u0;
            *(uint32_t*)(X + (r0 + 8) * SA2 + c * 2) = u1;
        }
    }
}

// ---------------- 32x32 warp-tile (edge kernel, 8 warps = 2M x 4N) ----------
template <int KTOT, int SA, int SW>
__device__ __forceinline__ void mma_layer64(const char* A, const char* W,
                                            float acc[2][4][4], int wm, int wn, int lane) {
    int row_off = (lane & 7) + ((lane >> 3) & 1) * 8;
    int col_off = (lane >> 4) * 8;
#pragma unroll
    for (int k0 = 0; k0 < KTOT; k0 += 16) {
        uint32_t a[2][4];
#pragma unroll
        for (int mi = 0; mi < 2; mi++)
            ldsm4(a[mi], smem_u32(A + (wm * 32 + mi * 16 + row_off) * SA
                                     + (k0 + col_off) * 2));
        uint32_t b[2][4];
#pragma unroll
        for (int np = 0; np < 2; np++)
            ldsm4(b[np], smem_u32(W + (wn * 32 + np * 16 + row_off) * SW
                                     + (k0 + col_off) * 2));
#pragma unroll
        for (int mi = 0; mi < 2; mi++)
#pragma unroll
            for (int np = 0; np < 2; np++) {
                mma_bf16(acc[mi][2 * np],     a[mi], b[np][0], b[np][2]);
                mma_bf16(acc[mi][2 * np + 1], a[mi], b[np][1], b[np][3]);
            }
    }
}
__device__ __forceinline__ void init_bias4(float acc[2][4][4], const float* sb,
                                           int wn, int q) {
#pragma unroll
    for (int ni = 0; ni < 4; ni++) {
        int c = wn * 32 + ni * 8 + q * 2;
        float v0 = sb[c], v1 = sb[c + 1];
#pragma unroll
        for (int mi = 0; mi < 2; mi++) {
            acc[mi][ni][0] = v0; acc[mi][ni][1] = v1;
            acc[mi][ni][2] = v0; acc[mi][ni][3] = v1;
        }
    }
}
__device__ __forceinline__ void epi_gelu64(char* X, float acc[2][4][4],
                                           int wm, int wn, int g, int q) {
#pragma unroll
    for (int mi = 0; mi < 2; mi++) {
        int r0 = wm * 32 + mi * 16 + g;
#pragma unroll
        for (int ni = 0; ni < 4; ni++) {
            int c = wn * 32 + ni * 8 + q * 2;
            __nv_bfloat162 h0 = __floats2bfloat162_rn(gelu_exact(acc[mi][ni][0]),
                                                      gelu_exact(acc[mi][ni][1]));
            __nv_bfloat162 h1 = __floats2bfloat162_rn(gelu_exact(acc[mi][ni][2]),
                                                      gelu_exact(acc[mi][ni][3]));
            uint32_t u0, u1;
            memcpy(&u0, &h0, 4); memcpy(&u1, &h1, 4);
            *(uint32_t*)(X + r0 * SA2 + c * 2) = u0;
            *(uint32_t*)(X + (r0 + 8) * SA2 + c * 2) = u1;
        }
    }
}

// ============================================================================
// Edge kernel: persistent weights, 64-edge tiles
// ============================================================================
__global__ __launch_bounds__(NTHREADS, 1) void edge_kernel_p(
    const float* __restrict__ hV, const float* __restrict__ hE,
    const int* __restrict__ src, const int* __restrict__ dst,
    const float* __restrict__ W1, const float* __restrict__ b1,
    const float* __restrict__ W2, const float* __restrict__ b2,
    const float* __restrict__ W3, const float* __restrict__ b3)
{
    extern __shared__ char smem[];
    char* W1s = smem + EW1_OFF;
    char* W2s = smem + EW2_OFF;
    char* W3s = smem + EW3_OFF;
    char* XB  = smem + EX_OFF;      // X1 (SA1); X2 @0, X3 @EX3_OFF (SA2); MS fp32 @0

    __shared__ int   sidx[TEM2];
    __shared__ int   didx[TEM2];
    __shared__ float s_b1[HDIM], s_b2[HDIM], s_b3[HDIM];

    int tid = threadIdx.x;
    int wid = tid >> 5;
    int lane = tid & 31;
    int wm = wid & 1, wn = wid >> 1;     // 2M x 4N warp grid
    int g = lane >> 2, q = lane & 3;

    if (tid < HDIM) {
        s_b1[tid] = b1[tid]; s_b2[tid] = b2[tid]; s_b3[tid] = b3[tid];
    }
    // one-time weight staging (fp32 -> bf16 smem)
#pragma unroll 4
    for (int t = 0; t < 48; t++) {
        int idx = tid + t * NTHREADS;
        int n = idx / 96, c4 = idx % 96;
        st_bf16x4(W1s + n * SA1 + c4 * 8, *(const float4*)(W1 + (size_t)n * K1 + c4 * 4));
    }
#pragma unroll 4
    for (int t = 0; t < 16; t++) {
        int idx = tid + t * NTHREADS;
        int n = idx >> 5, c4 = idx & 31;
        st_bf16x4(W2s + n * SA2 + c4 * 8, *(const float4*)(W2 + (size_t)n * HDIM + c4 * 4));
        st_bf16x4(W3s + n * SA2 + c4 * 8, *(const float4*)(W3 + (size_t)n * HDIM + c4 * 4));
    }
    __syncthreads();

    for (int tile = blockIdx.x; tile < NTILES; tile += gridDim.x) {
        size_t e0 = (size_t)tile * TEM2;
        if (tid < TEM2)            sidx[tid]        = src[e0 + tid];
        else if (tid < 2 * TEM2)   didx[tid - TEM2] = dst[e0 + (tid - TEM2)];
        __syncthreads();

        // gather X1 = [hV[src] | hE | hV[dst]] -> bf16 (64 x 384, stride SA1)
#pragma unroll 4
        for (int t = 0; t < 24; t++) {
            int idx = tid + t * NTHREADS;   // 64 edges * 96 float4
            int e   = idx / 96;
            int c4  = idx % 96;
            const float* p;
            if (c4 < 32)       p = hV + (size_t)sidx[e] * HDIM + c4 * 4;
            else if (c4 < 64)  p = hE + (e0 + e) * HDIM + (c4 - 32) * 4;
            else               p = hV + (size_t)didx[e] * HDIM + (c4 - 64) * 4;
            st_bf16x4(XB + e * SA1 + c4 * 8, *(const float4*)p);
        }
        __syncthreads();

        float acc[2][4][4];

        // layer 1
        init_bias4(acc, s_b1, wn, q);
        mma_layer64<K1, SA1, SA1>(XB, W1s, acc, wm, wn, lane);
        __syncthreads();                      // all warps done reading X1
        epi_gelu64(XB, acc, wm, wn, g, q);    // X2 @0 (overwrites X1 head)
        __syncthreads();

        // layer 2
        init_bias4(acc, s_b2, wn, q);
        mma_layer64<HDIM, SA2, SA2>(XB, W2s, acc, wm, wn, lane);
        epi_gelu64(XB + EX3_OFF, acc, wm, wn, g, q);   // X3 (disjoint from X2)
        __syncthreads();                      // X3 complete

        // layer 3
        init_bias4(acc, s_b3, wn, q);
        mma_layer64<HDIM, SA2, SA2>(XB + EX3_OFF, W3s, acc, wm, wn, lane);
        __syncthreads();                      // all warps done reading X3

        // stage messages fp32 (MS @0, overlaps X2/X3 - safe after sync)
        float* MS = (float*)XB;
#pragma unroll
        for (int mi = 0; mi < 2; mi++) {
            int r0 = wm * 32 + mi * 16 + g;
#pragma unroll
            for (int ni = 0; ni < 4; ni++) {
                int c = wn * 32 + ni * 8 + q * 2;
                *(float2*)(MS + r0 * 132 + c)       = make_float2(acc[mi][ni][0], acc[mi][ni][1]);
                *(float2*)(MS + (r0 + 8) * 132 + c) = make_float2(acc[mi][ni][2], acc[mi][ni][3]);
            }
        }
        __syncthreads();

        // coalesced scatter-add
#pragma unroll 4
        for (int t = 0; t < 32; t++) {
            int idx = tid + t * NTHREADS;   // 64*128
            int e = idx >> 7;
            int o = idx & 127;
            atomicAdd(&g_nsum[(size_t)sidx[e] * HDIM + o], MS[e * 132 + o]);
        }
        if (tid < TEM2) atomicAdd(&g_cnt[sidx[tid]], 1.0f);
        __syncthreads();                      // protect sidx/XB for next tile
    }
}

// ============================================================================
// Node kernel: bf16 mma.sync FFN + fp32 LN / residuals (unchanged from R8)
// ============================================================================
__global__ __launch_bounds__(NTHREADS, 1) void node_kernel_mma(
    const float* __restrict__ hV,
    const float* __restrict__ ln1g, const float* __restrict__ ln1b,
    const float* __restrict__ ln2g, const float* __restrict__ ln2b,
    const float* __restrict__ Win,  const float* __restrict__ bin,
    const float* __restrict__ Wout, const float* __restrict__ bout,
    float* __restrict__ out)
{
    extern __shared__ char smem[];
    float* hs = (float*)smem;
    char*  X  = smem + NX_OFF;
    char*  Hb = smem + NH_OFF;
    char*  Wb = smem + NW_OFF;

    __shared__ float s_bout[HDIM];

    int tid = threadIdx.x;
    int wid = tid >> 5;
    int lane = tid & 31;
    int wm = wid & 3, wn = wid >> 2;
    int g = lane >> 2, q = lane & 3;
    int n0 = blockIdx.x * TNN;

    if (tid < HDIM) s_bout[tid] = bout[tid];

#pragma unroll 4
    for (int t = 0; t < 64; t++) {
        int idx = tid + t * NTHREADS;
        int n = idx >> 7, o = idx & 127;
        int gn = n0 + n;
        float v = 0.0f;
        if (gn < NNODES) {
            float c = fmaxf(g_cnt[gn], 1.0f);
            v = hV[(size_t)gn * HDIM + o] + g_nsum[(size_t)gn * HDIM + o] / (c * SCALE_F);
        }
        hs[n * HS_STRIDE + o] = v;
    }
    __syncthreads();

    {
        int n = tid >> 1, h = tid & 1;
        float s = 0.0f, ss = 0.0f;
#pragma unroll
        for (int jj = 0; jj < 64; jj++) {
            float v = hs[n * HS_STRIDE + h * 64 + jj];
            s += v; ss += v * v;
        }
        s  += __shfl_xor_sync(0xffffffffu, s,  1);
        ss += __shfl_xor_sync(0xffffffffu, ss, 1);
        float mu   = s * (1.0f / 128.0f);
        float var  = ss * (1.0f / 128.0f) - mu * mu;
        float rstd = rsqrtf(var + LN_EPS);
#pragma unroll
        for (int jj = 0; jj < 64; jj += 2) {
            int o = h * 64 + jj;
            float v0 = (hs[n * HS_STRIDE + o]     - mu) * rstd * ln1g[o]     + ln1b[o];
            float v1 = (hs[n * HS_STRIDE + o + 1] - mu) * rstd * ln1g[o + 1] + ln1b[o + 1];
            hs[n * HS_STRIDE + o]     = v0;
            hs[n * HS_STRIDE + o + 1] = v1;
            __nv_bfloat162 hh = __floats2bfloat162_rn(v0, v1);
            uint32_t u; memcpy(&u, &hh, 4);
            *(uint32_t*)(X + n * SA2 + o * 2) = u;
        }
    }

    float dh[2][8][4];
    init_bias(dh, s_bout, wn, q);

    for (int nb = 0; nb < 4; nb++) {
        __syncthreads();
#pragma unroll 4
        for (int t = 0; t < 16; t++) {
            int idx = tid + t * NTHREADS;
            int n = idx >> 5, c4 = idx & 31;
            st_bf16x4(Wb + n * SA2 + c4 * 8,
                      *(const float4*)(Win + (size_t)(nb * 128 + n) * HDIM + c4 * 4));
        }
        __syncthreads();

        float acc[2][8][4];
        init_bias(acc, bin + nb * 128, wn, q);
        mma_layer<HDIM, SA2, SA2>(X, Wb, acc, wm, wn, lane);
        __syncthreads();
        epi_gelu(Hb, acc, wm, wn, g, q);

#pragma unroll 4
        for (int t = 0; t < 16; t++) {
            int idx = tid + t * NTHREADS;
            int n = idx >> 5, c4 = idx & 31;
            st_bf16x4(Wb + n * SA2 + c4 * 8,
                      *(const float4*)(Wout + (size_t)n * FFDIM + nb * 128 + c4 * 4));
        }
        __syncthreads();

        mma_layer<HDIM, SA2, SA2>(Hb, Wb, dh, wm, wn, lane);
    }
    __syncthreads();

    float* zs = (float*)X;
#pragma unroll
    for (int mi = 0; mi < 2; mi++) {
        int r0 = wm * 32 + mi * 16 + g;
#pragma unroll
        for (int ni = 0; ni < 8; ni++) {
            int c = wn * 64 + ni * 8 + q * 2;
            zs[r0 * 132 + c]           = dh[mi][ni][0] + hs[r0 * HS_STRIDE + c];
            zs[r0 * 132 + c + 1]       = dh[mi][ni][1] + hs[r0 * HS_STRIDE + c + 1];
            zs[(r0 + 8) * 132 + c]     = dh[mi][ni][2] + hs[(r0 + 8) * HS_STRIDE + c];
            zs[(r0 + 8) * 132 + c + 1] = dh[mi][ni][3] + hs[(r0 + 8) * HS_STRIDE + c + 1];
        }
    }
    __syncthreads();

    {
        int n = tid >> 1, h = tid & 1;
        float s = 0.0f, ss = 0.0f;
#pragma unroll
        for (int jj = 0; jj < 64; jj++) {
            float v = zs[n * 132 + h * 64 + jj];
            s += v; ss += v * v;
        }
        s  += __shfl_xor_sync(0xffffffffu, s,  1);
        ss += __shfl_xor_sync(0xffffffffu, ss, 1);
        float mu   = s * (1.0f / 128.0f);
        float var  = ss * (1.0f / 128.0f) - mu * mu;
        float rstd = rsqrtf(var + LN_EPS);
        int gn = n0 + n;
        if (gn < NNODES) {
#pragma unroll
            for (int jj = 0; jj < 64; jj++) {
                int o = h * 64 + jj;
                float v = zs[n * 132 + o];
                out[(size_t)gn * HDIM + o] = (v - mu) * rstd * ln2g[o] + ln2b[o];
            }
        }
    }
}

// ============================================================================
// Launch
// ============================================================================
extern "C" void kernel_launch(void* const* d_in, const int* in_sizes, int n_in,
                              void* d_out, int out_size)
{
    const float* hV   = (const float*)d_in[0];
    const float* hE   = (const float*)d_in[1];
    const int*   src  = (const int*)  d_in[2];
    const int*   dst  = (const int*)  d_in[4];
    const float* W1   = (const float*)d_in[5];
    const float* b1   = (const float*)d_in[6];
    const float* W2   = (const float*)d_in[7];
    const float* b2   = (const float*)d_in[8];
    const float* W3   = (const float*)d_in[9];
    const float* b3   = (const float*)d_in[10];
    const float* ln1g = (const float*)d_in[11];
    const float* ln1b = (const float*)d_in[12];
    const float* ln2g = (const float*)d_in[13];
    const float* ln2b = (const float*)d_in[14];
    const float* Win  = (const float*)d_in[15];
    const float* bin  = (const float*)d_in[16];
    const float* Wout = (const float*)d_in[17];
    const float* bout = (const float*)d_in[18];
    float* out = (float*)d_out;

    cudaFuncSetAttribute(edge_kernel_p, cudaFuncAttributeMaxDynamicSharedMemorySize, EDGE_SMEM);
    cudaFuncSetAttribute(node_kernel_mma, cudaFuncAttributeMaxDynamicSharedMemorySize, NODE_SMEM);

    void* nsum_p = nullptr;
    void* cnt_p  = nullptr;
    cudaGetSymbolAddress(&nsum_p, g_nsum);
    cudaGetSymbolAddress(&cnt_p,  g_cnt);
    cudaMemsetAsync(nsum_p, 0, sizeof(float) * (size_t)NNODES * HDIM);
    cudaMemsetAsync(cnt_p,  0, sizeof(float) * NNODES);

    edge_kernel_p<<<GRID_E, NTHREADS, EDGE_SMEM>>>(hV, hE, src, dst,
                                                   W1, b1, W2, b2, W3, b3);
    node_kernel_mma<<<(NNODES + TNN - 1) / TNN, NTHREADS, NODE_SMEM>>>(
        hV, ln1g, ln1b, ln2g, ln2b, Win, bin, Wout, bout, out);
}

// round 10
// speedup vs baseline: 5.8651x; 1.5089x over previous
#include <cuda_runtime.h>
#include <cuda_bf16.h>
#include <math.h>
#include <stdint.h>
#include <string.h>

#define EDGES    800000
#define NNODES   50000
#define HDIM     128
#define K1       384
#define FFDIM    512
#define TEM2     64
#define NTILES   (EDGES / TEM2)
#define GRID_E   148
#define TNN      128
#define NTH      512
#define SCALE_F  30.0f
#define LN_EPS   1e-5f

#define SA1 784
#define SA2 272

// edge smem layout (bytes)
#define EW1_OFF  0
#define EW2_OFF  (128 * SA1)
#define EW3_OFF  (EW2_OFF + 128 * SA2)
#define EX_OFF   (EW3_OFF + 128 * SA2)
#define EX3_OFF  (64 * SA2)
#define EDGE_SMEM (EX_OFF + 64 * SA1)      // 220160

// node smem layout (bytes)
#define HS_STRIDE 132
#define HS_BYTES  (TNN * HS_STRIDE * 4)
#define NX_OFF    HS_BYTES
#define NH_OFF    (NX_OFF + 128 * SA2)
#define NW_OFF    (NH_OFF + 128 * SA2)
#define NODE_SMEM (NW_OFF + 128 * SA2)

__device__ float g_nsum[(size_t)NNODES * HDIM];
__device__ float g_cnt[NNODES];

__device__ __forceinline__ float gelu_exact(float x) {
    return 0.5f * x * (1.0f + erff(x * 0.70710678118654752440f));
}
__device__ __forceinline__ uint32_t smem_u32(const void* p) {
    uint32_t a;
    asm("{ .reg .u64 t; cvta.to.shared.u64 t, %1; cvt.u32.u64 %0, t; }" : "=r"(a) : "l"(p));
    return a;
}
__device__ __forceinline__ void ldsm4(uint32_t r[4], uint32_t addr) {
    asm volatile("ldmatrix.sync.aligned.m8n8.x4.shared.b16 {%0,%1,%2,%3}, [%4];"
                 : "=r"(r[0]), "=r"(r[1]), "=r"(r[2]), "=r"(r[3]) : "r"(addr));
}
__device__ __forceinline__ void mma_bf16(float c[4], const uint32_t a[4],
                                         uint32_t b0, uint32_t b1) {
    asm volatile("mma.sync.aligned.m16n8k16.row.col.f32.bf16.bf16.f32 "
                 "{%0,%1,%2,%3}, {%4,%5,%6,%7}, {%8,%9}, {%0,%1,%2,%3};"
                 : "+f"(c[0]), "+f"(c[1]), "+f"(c[2]), "+f"(c[3])
                 : "r"(a[0]), "r"(a[1]), "r"(a[2]), "r"(a[3]), "r"(b0), "r"(b1));
}
__device__ __forceinline__ void st_bf16x4(char* dst, float4 v) {
    __nv_bfloat162 h0 = __floats2bfloat162_rn(v.x, v.y);
    __nv_bfloat162 h1 = __floats2bfloat162_rn(v.z, v.w);
    uint32_t u0, u1;
    memcpy(&u0, &h0, 4); memcpy(&u1, &h1, 4);
    *(uint2*)dst = make_uint2(u0, u1);
}

// generic warp tile: M = 32 (2 x m16), N = NP*16
template <int KTOT, int SA, int SW, int NP>
__device__ __forceinline__ void mma_tile(const char* A, const char* W,
                                         float (&acc)[2][2 * NP][4],
                                         int wm, int wn, int lane) {
    int row_off = (lane & 7) + ((lane >> 3) & 1) * 8;
    int col_off = (lane >> 4) * 8;
#pragma unroll
    for (int k0 = 0; k0 < KTOT; k0 += 16) {
        uint32_t a[2][4];
#pragma unroll
        for (int mi = 0; mi < 2; mi++)
            ldsm4(a[mi], smem_u32(A + (wm * 32 + mi * 16 + row_off) * SA
                                     + (k0 + col_off) * 2));
        uint32_t b[NP][4];
#pragma unroll
        for (int np = 0; np < NP; np++)
            ldsm4(b[np], smem_u32(W + (wn * 16 * NP + np * 16 + row_off) * SW
                                     + (k0 + col_off) * 2));
#pragma unroll
        for (int mi = 0; mi < 2; mi++)
#pragma unroll
            for (int np = 0; np < NP; np++) {
                mma_bf16(acc[mi][2 * np],     a[mi], b[np][0], b[np][2]);
                mma_bf16(acc[mi][2 * np + 1], a[mi], b[np][1], b[np][3]);
            }
    }
}
template <int NP>
__device__ __forceinline__ void init_bias(float (&acc)[2][2 * NP][4],
                                          const float* sb, int wn, int q) {
#pragma unroll
    for (int ni = 0; ni < 2 * NP; ni++) {
        int c = wn * 16 * NP + ni * 8 + q * 2;
        float v0 = sb[c], v1 = sb[c + 1];
#pragma unroll
        for (int mi = 0; mi < 2; mi++) {
            acc[mi][ni][0] = v0; acc[mi][ni][1] = v1;
            acc[mi][ni][2] = v0; acc[mi][ni][3] = v1;
        }
    }
}
template <int NP>
__device__ __forceinline__ void epi_gelu(char* X, float (&acc)[2][2 * NP][4],
                                         int wm, int wn, int g, int q) {
#pragma unroll
    for (int mi = 0; mi < 2; mi++) {
        int r0 = wm * 32 + mi * 16 + g;
#pragma unroll
        for (int ni = 0; ni < 2 * NP; ni++) {
            int c = wn * 16 * NP + ni * 8 + q * 2;
            __nv_bfloat162 h0 = __floats2bfloat162_rn(gelu_exact(acc[mi][ni][0]),
                                                      gelu_exact(acc[mi][ni][1]));
            __nv_bfloat162 h1 = __floats2bfloat162_rn(gelu_exact(acc[mi][ni][2]),
                                                      gelu_exact(acc[mi][ni][3]));
            uint32_t u0, u1;
            memcpy(&u0, &h0, 4); memcpy(&u1, &h1, 4);
            *(uint32_t*)(X + r0 * SA2 + c * 2) = u0;
            *(uint32_t*)(X + (r0 + 8) * SA2 + c * 2) = u1;
        }
    }
}

// ============================================================================
// Edge kernel: persistent weights, 512 threads, hE+idx prefetch pipeline
// ============================================================================
__global__ __launch_bounds__(NTH, 1) void edge_kernel_p(
    const float* __restrict__ hV, const float* __restrict__ hE,
    const int* __restrict__ src, const int* __restrict__ dst,
    const float* __restrict__ W1, const float* __restrict__ b1,
    const float* __restrict__ W2, const float* __restrict__ b2,
    const float* __restrict__ W3, const float* __restrict__ b3)
{
    extern __shared__ char smem[];
    char* W1s = smem + EW1_OFF;
    char* W2s = smem + EW2_OFF;
    char* W3s = smem + EW3_OFF;
    char* XB  = smem + EX_OFF;

    __shared__ int   sidx[2][TEM2];
    __shared__ int   didx[2][TEM2];
    __shared__ float s_b1[HDIM], s_b2[HDIM], s_b3[HDIM];

    int tid = threadIdx.x;
    int wid = tid >> 5;
    int lane = tid & 31;
    int wm = wid & 1, wn = wid >> 1;     // 2M x 8N
    int g = lane >> 2, q = lane & 3;

    if (tid < HDIM) {
        s_b1[tid] = b1[tid]; s_b2[tid] = b2[tid]; s_b3[tid] = b3[tid];
    }
    // one-time weight staging
#pragma unroll 4
    for (int t = 0; t < 24; t++) {
        int idx = tid + t * NTH;
        int n = idx / 96, c4 = idx % 96;
        st_bf16x4(W1s + n * SA1 + c4 * 8, *(const float4*)(W1 + (size_t)n * K1 + c4 * 4));
    }
#pragma unroll 4
    for (int t = 0; t < 8; t++) {
        int idx = tid + t * NTH;
        int n = idx >> 5, c4 = idx & 31;
        st_bf16x4(W2s + n * SA2 + c4 * 8, *(const float4*)(W2 + (size_t)n * HDIM + c4 * 4));
        st_bf16x4(W3s + n * SA2 + c4 * 8, *(const float4*)(W3 + (size_t)n * HDIM + c4 * 4));
    }

    // prologue: idx + hE prefetch for first tile
    int tile0 = blockIdx.x;
    float4 pf[4];
    int pe[4], pc[4];                      // (edge, float4-slot) of each prefetched vec
    {
        size_t e0 = (size_t)tile0 * TEM2;
        if (tid < TEM2)             sidx[0][tid]        = src[e0 + tid];
        else if (tid < 2 * TEM2)    didx[0][tid - TEM2] = dst[e0 + (tid - TEM2)];
#pragma unroll
        for (int t = 0; t < 4; t++) {
            int idx = tid + t * NTH;       // 2048 = 64 * 32
            pe[t] = idx >> 5; pc[t] = idx & 31;
            pf[t] = *(const float4*)(hE + (e0 + pe[t]) * HDIM + pc[t] * 4);
        }
    }
    __syncthreads();

    int p = 0;
    for (int tile = tile0; tile < NTILES; tile += GRID_E, p ^= 1) {
        const int* si = sidx[p];
        const int* di = didx[p];

        // ---- gather: store prefetched hE, demand-load hV ----
#pragma unroll
        for (int t = 0; t < 4; t++)
            st_bf16x4(XB + pe[t] * SA1 + (32 + pc[t]) * 8, pf[t]);
#pragma unroll 4
        for (int t = 0; t < 8; t++) {
            int idx = tid + t * NTH;       // 4096 = 64 * 64
            int e = idx >> 6, c = idx & 63;
            const float* ptr = (c < 32)
                ? hV + (size_t)si[e] * HDIM + c * 4
                : hV + (size_t)di[e] * HDIM + (c - 32) * 4;
            int slot = (c < 32) ? c : (c + 32);
            st_bf16x4(XB + e * SA1 + slot * 8, *(const float4*)ptr);
        }
        __syncthreads();

        // ---- issue next-tile prefetch (hidden under MMA phases) ----
        int tnext = tile + GRID_E;
        if (tnext < NTILES) {
            size_t e0n = (size_t)tnext * TEM2;
            if (tid < TEM2)           sidx[p ^ 1][tid]        = src[e0n + tid];
            else if (tid < 2 * TEM2)  didx[p ^ 1][tid - TEM2] = dst[e0n + (tid - TEM2)];
#pragma unroll
            for (int t = 0; t < 4; t++)
                pf[t] = *(const float4*)(hE + (e0n + pe[t]) * HDIM + pc[t] * 4);
        }

        float acc[2][2][4];

        // layer 1
        init_bias<1>(acc, s_b1, wn, q);
        mma_tile<K1, SA1, SA1, 1>(XB, W1s, acc, wm, wn, lane);
        __syncthreads();
        epi_gelu<1>(XB, acc, wm, wn, g, q);          // X2 @0 (SA2)
        __syncthreads();

        // layer 2
        init_bias<1>(acc, s_b2, wn, q);
        mma_tile<HDIM, SA2, SA2, 1>(XB, W2s, acc, wm, wn, lane);
        epi_gelu<1>(XB + EX3_OFF, acc, wm, wn, g, q);  // X3 (disjoint)
        __syncthreads();

        // layer 3
        init_bias<1>(acc, s_b3, wn, q);
        mma_tile<HDIM, SA2, SA2, 1>(XB + EX3_OFF, W3s, acc, wm, wn, lane);
        __syncthreads();

        // stage messages fp32
        float* MS = (float*)XB;
#pragma unroll
        for (int mi = 0; mi < 2; mi++) {
            int r0 = wm * 32 + mi * 16 + g;
#pragma unroll
            for (int ni = 0; ni < 2; ni++) {
                int c = wn * 16 + ni * 8 + q * 2;
                *(float2*)(MS + r0 * 132 + c)       = make_float2(acc[mi][ni][0], acc[mi][ni][1]);
                *(float2*)(MS + (r0 + 8) * 132 + c) = make_float2(acc[mi][ni][2], acc[mi][ni][3]);
            }
        }
        __syncthreads();

        // coalesced scatter-add
#pragma unroll 4
        for (int t = 0; t < 16; t++) {
            int idx = tid + t * NTH;      // 8192
            int e = idx >> 7, o = idx & 127;
            atomicAdd(&g_nsum[(size_t)si[e] * HDIM + o], MS[e * 132 + o]);
        }
        if (tid < TEM2) atomicAdd(&g_cnt[si[tid]], 1.0f);
        __syncthreads();
    }
}

// ============================================================================
// Node kernel: 512 threads, bf16 mma FFN + fp32 LN / residuals
// ============================================================================
__global__ __launch_bounds__(NTH, 1) void node_kernel_mma(
    const float* __restrict__ hV,
    const float* __restrict__ ln1g, const float* __restrict__ ln1b,
    const float* __restrict__ ln2g, const float* __restrict__ ln2b,
    const float* __restrict__ Win,  const float* __restrict__ bin,
    const float* __restrict__ Wout, const float* __restrict__ bout,
    float* __restrict__ out)
{
    extern __shared__ char smem[];
    float* hs = (float*)smem;
    char*  X  = smem + NX_OFF;
    char*  Hb = smem + NH_OFF;
    char*  Wb = smem + NW_OFF;

    __shared__ float s_bout[HDIM];

    int tid = threadIdx.x;
    int wid = tid >> 5;
    int lane = tid & 31;
    int wm = wid & 3, wn = wid >> 2;     // 4M x 4N
    int g = lane >> 2, q = lane & 3;
    int n0 = blockIdx.x * TNN;

    if (tid < HDIM) s_bout[tid] = bout[tid];

#pragma unroll 4
    for (int t = 0; t < 32; t++) {
        int idx = tid + t * NTH;
        int n = idx >> 7, o = idx & 127;
        int gn = n0 + n;
        float v = 0.0f;
        if (gn < NNODES) {
            float c = fmaxf(g_cnt[gn], 1.0f);
            v = hV[(size_t)gn * HDIM + o] + g_nsum[(size_t)gn * HDIM + o] / (c * SCALE_F);
        }
        hs[n * HS_STRIDE + o] = v;
    }
    __syncthreads();

    // LN1: 4 lanes per row
    {
        int n = tid >> 2, q4 = tid & 3;
        float s = 0.0f, ss = 0.0f;
#pragma unroll
        for (int jj = 0; jj < 32; jj++) {
            float v = hs[n * HS_STRIDE + q4 * 32 + jj];
            s += v; ss += v * v;
        }
#pragma unroll
        for (int m = 1; m < 4; m <<= 1) {
            s  += __shfl_xor_sync(0xffffffffu, s,  m);
            ss += __shfl_xor_sync(0xffffffffu, ss, m);
        }
        float mu   = s * (1.0f / 128.0f);
        float var  = ss * (1.0f / 128.0f) - mu * mu;
        float rstd = rsqrtf(var + LN_EPS);
#pragma unroll
        for (int jj = 0; jj < 32; jj += 2) {
            int o = q4 * 32 + jj;
            float v0 = (hs[n * HS_STRIDE + o]     - mu) * rstd * ln1g[o]     + ln1b[o];
            float v1 = (hs[n * HS_STRIDE + o + 1] - mu) * rstd * ln1g[o + 1] + ln1b[o + 1];
            hs[n * HS_STRIDE + o]     = v0;
            hs[n * HS_STRIDE + o + 1] = v1;
            __nv_bfloat162 hh = __floats2bfloat162_rn(v0, v1);
            uint32_t u; memcpy(&u, &hh, 4);
            *(uint32_t*)(X + n * SA2 + o * 2) = u;
        }
    }

    float dh[2][4][4];
    init_bias<2>(dh, s_bout, wn, q);

    for (int nb = 0; nb < 4; nb++) {
        __syncthreads();
#pragma unroll 4
        for (int t = 0; t < 8; t++) {
            int idx = tid + t * NTH;
            int n = idx >> 5, c4 = idx & 31;
            st_bf16x4(Wb + n * SA2 + c4 * 8,
                      *(const float4*)(Win + (size_t)(nb * 128 + n) * HDIM + c4 * 4));
        }
        __syncthreads();

        float acc[2][4][4];
        init_bias<2>(acc, bin + nb * 128, wn, q);
        mma_tile<HDIM, SA2, SA2, 2>(X, Wb, acc, wm, wn, lane);
        __syncthreads();
        epi_gelu<2>(Hb, acc, wm, wn, g, q);

#pragma unroll 4
        for (int t = 0; t < 8; t++) {
            int idx = tid + t * NTH;
            int n = idx >> 5, c4 = idx & 31;
            st_bf16x4(Wb + n * SA2 + c4 * 8,
                      *(const float4*)(Wout + (size_t)n * FFDIM + nb * 128 + c4 * 4));
        }
        __syncthreads();

        mma_tile<HDIM, SA2, SA2, 2>(Hb, Wb, dh, wm, wn, lane);
    }
    __syncthreads();

    float* zs = (float*)X;
#pragma unroll
    for (int mi = 0; mi < 2; mi++) {
        int r0 = wm * 32 + mi * 16 + g;
#pragma unroll
        for (int ni = 0; ni < 4; ni++) {
            int c = wn * 32 + ni * 8 + q * 2;
            zs[r0 * 132 + c]           = dh[mi][ni][0] + hs[r0 * HS_STRIDE + c];
            zs[r0 * 132 + c + 1]       = dh[mi][ni][1] + hs[r0 * HS_STRIDE + c + 1];
            zs[(r0 + 8) * 132 + c]     = dh[mi][ni][2] + hs[(r0 + 8) * HS_STRIDE + c];
            zs[(r0 + 8) * 132 + c + 1] = dh[mi][ni][3] + hs[(r0 + 8) * HS_STRIDE + c + 1];
        }
    }
    __syncthreads();

    // LN2 + store
    {
        int n = tid >> 2, q4 = tid & 3;
        float s = 0.0f, ss = 0.0f;
#pragma unroll
        for (int jj = 0; jj < 32; jj++) {
            float v = zs[n * 132 + q4 * 32 + jj];
            s += v; ss += v * v;
        }
#pragma unroll
        for (int m = 1; m < 4; m <<= 1) {
            s  += __shfl_xor_sync(0xffffffffu, s,  m);
            ss += __shfl_xor_sync(0xffffffffu, ss, m);
        }
        float mu   = s * (1.0f / 128.0f);
        float var  = ss * (1.0f / 128.0f) - mu * mu;
        float rstd = rsqrtf(var + LN_EPS);
        int gn = n0 + n;
        if (gn < NNODES) {
#pragma unroll
            for (int jj = 0; jj < 32; jj++) {
                int o = q4 * 32 + jj;
                float v = zs[n * 132 + o];
                out[(size_t)gn * HDIM + o] = (v - mu) * rstd * ln2g[o] + ln2b[o];
            }
        }
    }
}

// ============================================================================
// Launch
// ============================================================================
extern "C" void kernel_launch(void* const* d_in, const int* in_sizes, int n_in,
                              void* d_out, int out_size)
{
    const float* hV   = (const float*)d_in[0];
    const float* hE   = (const float*)d_in[1];
    const int*   src  = (const int*)  d_in[2];
    const int*   dst  = (const int*)  d_in[4];
    const float* W1   = (const float*)d_in[5];
    const float* b1   = (const float*)d_in[6];
    const float* W2   = (const float*)d_in[7];
    const float* b2   = (const float*)d_in[8];
    const float* W3   = (const float*)d_in[9];
    const float* b3   = (const float*)d_in[10];
    const float* ln1g = (const float*)d_in[11];
    const float* ln1b = (const float*)d_in[12];
    const float* ln2g = (const float*)d_in[13];
    const float* ln2b = (const float*)d_in[14];
    const float* Win  = (const float*)d_in[15];
    const float* bin  = (const float*)d_in[16];
    const float* Wout = (const float*)d_in[17];
    const float* bout = (const float*)d_in[18];
    float* out = (float*)d_out;

    cudaFuncSetAttribute(edge_kernel_p, cudaFuncAttributeMaxDynamicSharedMemorySize, EDGE_SMEM);
    cudaFuncSetAttribute(node_kernel_mma, cudaFuncAttributeMaxDynamicSharedMemorySize, NODE_SMEM);

    void* nsum_p = nullptr;
    void* cnt_p  = nullptr;
    cudaGetSymbolAddress(&nsum_p, g_nsum);
    cudaGetSymbolAddress(&cnt_p,  g_cnt);
    cudaMemsetAsync(nsum_p, 0, sizeof(float) * (size_t)NNODES * HDIM);
    cudaMemsetAsync(cnt_p,  0, sizeof(float) * NNODES);

    edge_kernel_p<<<GRID_E, NTH, EDGE_SMEM>>>(hV, hE, src, dst,
                                              W1, b1, W2, b2, W3, b3);
    node_kernel_mma<<<(NNODES + TNN - 1) / TNN, NTH, NODE_SMEM>>>(
        hV, ln1g, ln1b, ln2g, ln2b, Win, bin, Wout, bout, out);
}

// round 11
// speedup vs baseline: 6.1709x; 1.0521x over previous
#include <cuda_runtime.h>
#include <cuda_bf16.h>
#include <math.h>
#include <stdint.h>
#include <string.h>

#define EDGES    800000
#define NNODES   50000
#define HDIM     128
#define K1       384
#define FFDIM    512
#define TEM2     64
#define NTILES   (EDGES / TEM2)
#define GRID_E   148
#define TNN      128
#define NTH      512
#define SCALE_F  30.0f
#define LN_EPS   1e-5f

#define SA1 784
#define SA2 272

// edge smem layout (bytes)
#define EW1_OFF  0
#define EW2_OFF  (128 * SA1)
#define EW3_OFF  (EW2_OFF + 128 * SA2)
#define EX_OFF   (EW3_OFF + 128 * SA2)
#define EX3_OFF  (64 * SA2)
#define EDGE_SMEM (EX_OFF + 64 * SA1)      // 220160

// node smem layout (bytes)
#define HS_STRIDE 132
#define HS_BYTES  (TNN * HS_STRIDE * 4)
#define NX_OFF    HS_BYTES
#define NH_OFF    (NX_OFF + 128 * SA2)
#define NW_OFF    (NH_OFF + 128 * SA2)
#define NODE_SMEM (NW_OFF + 128 * SA2)

__device__ float g_nsum[(size_t)NNODES * HDIM];
__device__ float g_cnt[NNODES];

__device__ __forceinline__ float gelu_exact(float x) {
    return 0.5f * x * (1.0f + erff(x * 0.70710678118654752440f));
}
__device__ __forceinline__ uint32_t smem_u32(const void* p) {
    uint32_t a;
    asm("{ .reg .u64 t; cvta.to.shared.u64 t, %1; cvt.u32.u64 %0, t; }" : "=r"(a) : "l"(p));
    return a;
}
__device__ __forceinline__ void ldsm4(uint32_t r[4], uint32_t addr) {
    asm volatile("ldmatrix.sync.aligned.m8n8.x4.shared.b16 {%0,%1,%2,%3}, [%4];"
                 : "=r"(r[0]), "=r"(r[1]), "=r"(r[2]), "=r"(r[3]) : "r"(addr));
}
__device__ __forceinline__ void mma_bf16(float c[4], const uint32_t a[4],
                                         uint32_t b0, uint32_t b1) {
    asm volatile("mma.sync.aligned.m16n8k16.row.col.f32.bf16.bf16.f32 "
                 "{%0,%1,%2,%3}, {%4,%5,%6,%7}, {%8,%9}, {%0,%1,%2,%3};"
                 : "+f"(c[0]), "+f"(c[1]), "+f"(c[2]), "+f"(c[3])
                 : "r"(a[0]), "r"(a[1]), "r"(a[2]), "r"(a[3]), "r"(b0), "r"(b1));
}
__device__ __forceinline__ void st_bf16x4(char* dst, float4 v) {
    __nv_bfloat162 h0 = __floats2bfloat162_rn(v.x, v.y);
    __nv_bfloat162 h1 = __floats2bfloat162_rn(v.z, v.w);
    uint32_t u0, u1;
    memcpy(&u0, &h0, 4); memcpy(&u1, &h1, 4);
    *(uint2*)dst = make_uint2(u0, u1);
}

// generic warp tile: M = 32 (2 x m16), N = NP*16
template <int KTOT, int SA, int SW, int NP>
__device__ __forceinline__ void mma_tile(const char* A, const char* W,
                                         float (&acc)[2][2 * NP][4],
                                         int wm, int wn, int lane) {
    int row_off = (lane & 7) + ((lane >> 3) & 1) * 8;
    int col_off = (lane >> 4) * 8;
#pragma unroll
    for (int k0 = 0; k0 < KTOT; k0 += 16) {
        uint32_t a[2][4];
#pragma unroll
        for (int mi = 0; mi < 2; mi++)
            ldsm4(a[mi], smem_u32(A + (wm * 32 + mi * 16 + row_off) * SA
                                     + (k0 + col_off) * 2));
        uint32_t b[NP][4];
#pragma unroll
        for (int np = 0; np < NP; np++)
            ldsm4(b[np], smem_u32(W + (wn * 16 * NP + np * 16 + row_off) * SW
                                     + (k0 + col_off) * 2));
#pragma unroll
        for (int mi = 0; mi < 2; mi++)
#pragma unroll
            for (int np = 0; np < NP; np++) {
                mma_bf16(acc[mi][2 * np],     a[mi], b[np][0], b[np][2]);
                mma_bf16(acc[mi][2 * np + 1], a[mi], b[np][1], b[np][3]);
            }
    }
}
template <int NP>
__device__ __forceinline__ void init_bias(float (&acc)[2][2 * NP][4],
                                          const float* sb, int wn, int q) {
#pragma unroll
    for (int ni = 0; ni < 2 * NP; ni++) {
        int c = wn * 16 * NP + ni * 8 + q * 2;
        float v0 = sb[c], v1 = sb[c + 1];
#pragma unroll
        for (int mi = 0; mi < 2; mi++) {
            acc[mi][ni][0] = v0; acc[mi][ni][1] = v1;
            acc[mi][ni][2] = v0; acc[mi][ni][3] = v1;
        }
    }
}
template <int NP>
__device__ __forceinline__ void epi_gelu(char* X, float (&acc)[2][2 * NP][4],
                                         int wm, int wn, int g, int q) {
#pragma unroll
    for (int mi = 0; mi < 2; mi++) {
        int r0 = wm * 32 + mi * 16 + g;
#pragma unroll
        for (int ni = 0; ni < 2 * NP; ni++) {
            int c = wn * 16 * NP + ni * 8 + q * 2;
            __nv_bfloat162 h0 = __floats2bfloat162_rn(gelu_exact(acc[mi][ni][0]),
                                                      gelu_exact(acc[mi][ni][1]));
            __nv_bfloat162 h1 = __floats2bfloat162_rn(gelu_exact(acc[mi][ni][2]),
                                                      gelu_exact(acc[mi][ni][3]));
            uint32_t u0, u1;
            memcpy(&u0, &h0, 4); memcpy(&u1, &h1, 4);
            *(uint32_t*)(X + r0 * SA2 + c * 2) = u0;
            *(uint32_t*)(X + (r0 + 8) * SA2 + c * 2) = u1;
        }
    }
}

// prefetch one tile's gather data fully into registers
// hV: idx = tid + t*NTH (t<8): e = idx>>6, c = idx&63 ; c<32 -> src col c ; else dst col c-32
// hE: idx = tid + t*NTH (t<4): e = idx>>5, c = idx&31
__device__ __forceinline__ void prefetch_tile(
    size_t e0, const float* __restrict__ hV, const float* __restrict__ hE,
    const int* __restrict__ src, const int* __restrict__ dst,
    int tid, float4 (&hv)[8], float4 (&he)[4])
{
#pragma unroll
    for (int t = 0; t < 8; t++) {
        int idx = tid + t * NTH;
        int e = idx >> 6, c = idx & 63;
        int node = (c < 32) ? src[e0 + e] : dst[e0 + e];
        int cc = c & 31;
        hv[t] = *(const float4*)(hV + (size_t)node * HDIM + cc * 4);
    }
#pragma unroll
    for (int t = 0; t < 4; t++) {
        int idx = tid + t * NTH;
        int e = idx >> 5, c = idx & 31;
        he[t] = *(const float4*)(hE + (e0 + e) * HDIM + c * 4);
    }
}

// ============================================================================
// Edge kernel: persistent weights, full register gather prefetch,
// direct-from-accumulator float2 atomic scatter
// ============================================================================
__global__ __launch_bounds__(NTH, 1) void edge_kernel_p(
    const float* __restrict__ hV, const float* __restrict__ hE,
    const int* __restrict__ src, const int* __restrict__ dst,
    const float* __restrict__ W1, const float* __restrict__ b1,
    const float* __restrict__ W2, const float* __restrict__ b2,
    const float* __restrict__ W3, const float* __restrict__ b3)
{
    extern __shared__ char smem[];
    char* W1s = smem + EW1_OFF;
    char* W2s = smem + EW2_OFF;
    char* W3s = smem + EW3_OFF;
    char* XB  = smem + EX_OFF;

    __shared__ int   sidx[2][TEM2];
    __shared__ float s_b1[HDIM], s_b2[HDIM], s_b3[HDIM];

    int tid = threadIdx.x;
    int wid = tid >> 5;
    int lane = tid & 31;
    int wm = wid & 1, wn = wid >> 1;     // 2M x 8N
    int g = lane >> 2, q = lane & 3;

    if (tid < HDIM) {
        s_b1[tid] = b1[tid]; s_b2[tid] = b2[tid]; s_b3[tid] = b3[tid];
    }
    // one-time weight staging
#pragma unroll 4
    for (int t = 0; t < 24; t++) {
        int idx = tid + t * NTH;
        int n = idx / 96, c4 = idx % 96;
        st_bf16x4(W1s + n * SA1 + c4 * 8, *(const float4*)(W1 + (size_t)n * K1 + c4 * 4));
    }
#pragma unroll 4
    for (int t = 0; t < 8; t++) {
        int idx = tid + t * NTH;
        int n = idx >> 5, c4 = idx & 31;
        st_bf16x4(W2s + n * SA2 + c4 * 8, *(const float4*)(W2 + (size_t)n * HDIM + c4 * 4));
        st_bf16x4(W3s + n * SA2 + c4 * 8, *(const float4*)(W3 + (size_t)n * HDIM + c4 * 4));
    }

    // prologue: full prefetch of first tile
    int tile0 = blockIdx.x;
    float4 hv[8], he[4];
    {
        size_t e0 = (size_t)tile0 * TEM2;
        if (tid < TEM2) sidx[0][tid] = src[e0 + tid];
        prefetch_tile(e0, hV, hE, src, dst, tid, hv, he);
    }
    __syncthreads();

    int p = 0;
    for (int tile = tile0; tile < NTILES; tile += GRID_E, p ^= 1) {
        const int* si = sidx[p];

        // ---- gather: pure STS from prefetched registers ----
#pragma unroll
        for (int t = 0; t < 8; t++) {
            int idx = tid + t * NTH;
            int e = idx >> 6, c = idx & 63;
            int slot = (c < 32) ? c : (c + 32);     // src cols 0-31, dst cols 64-95
            st_bf16x4(XB + e * SA1 + slot * 8, hv[t]);
        }
#pragma unroll
        for (int t = 0; t < 4; t++) {
            int idx = tid + t * NTH;
            int e = idx >> 5, c = idx & 31;
            st_bf16x4(XB + e * SA1 + (32 + c) * 8, he[t]);
        }
        __syncthreads();

        // ---- issue next tile's prefetch (hidden under MMA phases) ----
        int tnext = tile + GRID_E;
        if (tnext < NTILES) {
            size_t e0n = (size_t)tnext * TEM2;
            if (tid < TEM2) sidx[p ^ 1][tid] = src[e0n + tid];
            prefetch_tile(e0n, hV, hE, src, dst, tid, hv, he);
        }

        float acc[2][2][4];

        // layer 1
        init_bias<1>(acc, s_b1, wn, q);
        mma_tile<K1, SA1, SA1, 1>(XB, W1s, acc, wm, wn, lane);
        __syncthreads();
        epi_gelu<1>(XB, acc, wm, wn, g, q);          // X2 @0 (SA2)
        __syncthreads();

        // layer 2
        init_bias<1>(acc, s_b2, wn, q);
        mma_tile<HDIM, SA2, SA2, 1>(XB, W2s, acc, wm, wn, lane);
        epi_gelu<1>(XB + EX3_OFF, acc, wm, wn, g, q);  // X3 (disjoint)
        __syncthreads();

        // layer 3
        init_bias<1>(acc, s_b3, wn, q);
        mma_tile<HDIM, SA2, SA2, 1>(XB + EX3_OFF, W3s, acc, wm, wn, lane);

        // ---- direct scatter from accumulators (float2 vector atomics) ----
#pragma unroll
        for (int mi = 0; mi < 2; mi++) {
            int r0 = wm * 32 + mi * 16 + g;
            float* row0 = &g_nsum[(size_t)si[r0] * HDIM];
            float* row1 = &g_nsum[(size_t)si[r0 + 8] * HDIM];
#pragma unroll
            for (int ni = 0; ni < 2; ni++) {
                int c = wn * 16 + ni * 8 + q * 2;
                atomicAdd((float2*)(row0 + c), make_float2(acc[mi][ni][0], acc[mi][ni][1]));
                atomicAdd((float2*)(row1 + c), make_float2(acc[mi][ni][2], acc[mi][ni][3]));
            }
        }
        if (tid < TEM2) atomicAdd(&g_cnt[si[tid]], 1.0f);

        __syncthreads();    // all warps done reading X3 / si before next gather
    }
}

// ============================================================================
// Node kernel: 512 threads, bf16 mma FFN + fp32 LN / residuals (unchanged)
// ============================================================================
__global__ __launch_bounds__(NTH, 1) void node_kernel_mma(
    const float* __restrict__ hV,
    const float* __restrict__ ln1g, const float* __restrict__ ln1b,
    const float* __restrict__ ln2g, const float* __restrict__ ln2b,
    const float* __restrict__ Win,  const float* __restrict__ bin,
    const float* __restrict__ Wout, const float* __restrict__ bout,
    float* __restrict__ out)
{
    extern __shared__ char smem[];
    float* hs = (float*)smem;
    char*  X  = smem + NX_OFF;
    char*  Hb = smem + NH_OFF;
    char*  Wb = smem + NW_OFF;

    __shared__ float s_bout[HDIM];

    int tid = threadIdx.x;
    int wid = tid >> 5;
    int lane = tid & 31;
    int wm = wid & 3, wn = wid >> 2;     // 4M x 4N
    int g = lane >> 2, q = lane & 3;
    int n0 = blockIdx.x * TNN;

    if (tid < HDIM) s_bout[tid] = bout[tid];

#pragma unroll 4
    for (int t = 0; t < 32; t++) {
        int idx = tid + t * NTH;
        int n = idx >> 7, o = idx & 127;
        int gn = n0 + n;
        float v = 0.0f;
        if (gn < NNODES) {
            float c = fmaxf(g_cnt[gn], 1.0f);
            v = hV[(size_t)gn * HDIM + o] + g_nsum[(size_t)gn * HDIM + o] / (c * SCALE_F);
        }
        hs[n * HS_STRIDE + o] = v;
    }
    __syncthreads();

    // LN1: 4 lanes per row
    {
        int n = tid >> 2, q4 = tid & 3;
        float s = 0.0f, ss = 0.0f;
#pragma unroll
        for (int jj = 0; jj < 32; jj++) {
            float v = hs[n * HS_STRIDE + q4 * 32 + jj];
            s += v; ss += v * v;
        }
#pragma unroll
        for (int m = 1; m < 4; m <<= 1) {
            s  += __shfl_xor_sync(0xffffffffu, s,  m);
            ss += __shfl_xor_sync(0xffffffffu, ss, m);
        }
        float mu   = s * (1.0f / 128.0f);
        float var  = ss * (1.0f / 128.0f) - mu * mu;
        float rstd = rsqrtf(var + LN_EPS);
#pragma unroll
        for (int jj = 0; jj < 32; jj += 2) {
            int o = q4 * 32 + jj;
            float v0 = (hs[n * HS_STRIDE + o]     - mu) * rstd * ln1g[o]     + ln1b[o];
            float v1 = (hs[n * HS_STRIDE + o + 1] - mu) * rstd * ln1g[o + 1] + ln1b[o + 1];
            hs[n * HS_STRIDE + o]     = v0;
            hs[n * HS_STRIDE + o + 1] = v1;
            __nv_bfloat162 hh = __floats2bfloat162_rn(v0, v1);
            uint32_t u; memcpy(&u, &hh, 4);
            *(uint32_t*)(X + n * SA2 + o * 2) = u;
        }
    }

    float dh[2][4][4];
    init_bias<2>(dh, s_bout, wn, q);

    for (int nb = 0; nb < 4; nb++) {
        __syncthreads();
#pragma unroll 4
        for (int t = 0; t < 8; t++) {
            int idx = tid + t * NTH;
            int n = idx >> 5, c4 = idx & 31;
            st_bf16x4(Wb + n * SA2 + c4 * 8,
                      *(const float4*)(Win + (size_t)(nb * 128 + n) * HDIM + c4 * 4));
        }
        __syncthreads();

        float acc[2][4][4];
        init_bias<2>(acc, bin + nb * 128, wn, q);
        mma_tile<HDIM, SA2, SA2, 2>(X, Wb, acc, wm, wn, lane);
        __syncthreads();
        epi_gelu<2>(Hb, acc, wm, wn, g, q);

#pragma unroll 4
        for (int t = 0; t < 8; t++) {
            int idx = tid + t * NTH;
            int n = idx >> 5, c4 = idx & 31;
            st_bf16x4(Wb + n * SA2 + c4 * 8,
                      *(const float4*)(Wout + (size_t)n * FFDIM + nb * 128 + c4 * 4));
        }
        __syncthreads();

        mma_tile<HDIM, SA2, SA2, 2>(Hb, Wb, dh, wm, wn, lane);
    }
    __syncthreads();

    float* zs = (float*)X;
#pragma unroll
    for (int mi = 0; mi < 2; mi++) {
        int r0 = wm * 32 + mi * 16 + g;
#pragma unroll
        for (int ni = 0; ni < 4; ni++) {
            int c = wn * 32 + ni * 8 + q * 2;
            zs[r0 * 132 + c]           = dh[mi][ni][0] + hs[r0 * HS_STRIDE + c];
            zs[r0 * 132 + c + 1]       = dh[mi][ni][1] + hs[r0 * HS_STRIDE + c + 1];
            zs[(r0 + 8) * 132 + c]     = dh[mi][ni][2] + hs[(r0 + 8) * HS_STRIDE + c];
            zs[(r0 + 8) * 132 + c + 1] = dh[mi][ni][3] + hs[(r0 + 8) * HS_STRIDE + c + 1];
        }
    }
    __syncthreads();

    // LN2 + store
    {
        int n = tid >> 2, q4 = tid & 3;
        float s = 0.0f, ss = 0.0f;
#pragma unroll
        for (int jj = 0; jj < 32; jj++) {
            float v = zs[n * 132 + q4 * 32 + jj];
            s += v; ss += v * v;
        }
#pragma unroll
        for (int m = 1; m < 4; m <<= 1) {
            s  += __shfl_xor_sync(0xffffffffu, s,  m);
            ss += __shfl_xor_sync(0xffffffffu, ss, m);
        }
        float mu   = s * (1.0f / 128.0f);
        float var  = ss * (1.0f / 128.0f) - mu * mu;
        float rstd = rsqrtf(var + LN_EPS);
        int gn = n0 + n;
        if (gn < NNODES) {
#pragma unroll
            for (int jj = 0; jj < 32; jj++) {
                int o = q4 * 32 + jj;
                float v = zs[n * 132 + o];
                out[(size_t)gn * HDIM + o] = (v - mu) * rstd * ln2g[o] + ln2b[o];
            }
        }
    }
}

// ============================================================================
// Launch
// ============================================================================
extern "C" void kernel_launch(void* const* d_in, const int* in_sizes, int n_in,
                              void* d_out, int out_size)
{
    const float* hV   = (const float*)d_in[0];
    const float* hE   = (const float*)d_in[1];
    const int*   src  = (const int*)  d_in[2];
    const int*   dst  = (const int*)  d_in[4];
    const float* W1   = (const float*)d_in[5];
    const float* b1   = (const float*)d_in[6];
    const float* W2   = (const float*)d_in[7];
    const float* b2   = (const float*)d_in[8];
    const float* W3   = (const float*)d_in[9];
    const float* b3   = (const float*)d_in[10];
    const float* ln1g = (const float*)d_in[11];
    const float* ln1b = (const float*)d_in[12];
    const float* ln2g = (const float*)d_in[13];
    const float* ln2b = (const float*)d_in[14];
    const float* Win  = (const float*)d_in[15];
    const float* bin  = (const float*)d_in[16];
    const float* Wout = (const float*)d_in[17];
    const float* bout = (const float*)d_in[18];
    float* out = (float*)d_out;

    cudaFuncSetAttribute(edge_kernel_p, cudaFuncAttributeMaxDynamicSharedMemorySize, EDGE_SMEM);
    cudaFuncSetAttribute(node_kernel_mma, cudaFuncAttributeMaxDynamicSharedMemorySize, NODE_SMEM);

    void* nsum_p = nullptr;
    void* cnt_p  = nullptr;
    cudaGetSymbolAddress(&nsum_p, g_nsum);
    cudaGetSymbolAddress(&cnt_p,  g_cnt);
    cudaMemsetAsync(nsum_p, 0, sizeof(float) * (size_t)NNODES * HDIM);
    cudaMemsetAsync(cnt_p,  0, sizeof(float) * NNODES);

    edge_kernel_p<<<GRID_E, NTH, EDGE_SMEM>>>(hV, hE, src, dst,
                                              W1, b1, W2, b2, W3, b3);
    node_kernel_mma<<<(NNODES + TNN - 1) / TNN, NTH, NODE_SMEM>>>(
        hV, ln1g, ln1b, ln2g, ln2b, Win, bin, Wout, bout, out);
}

// round 13
// speedup vs baseline: 7.1025x; 1.1510x over previous
#include <cuda_runtime.h>
#include <cuda_bf16.h>
#include <math.h>
#include <stdint.h>
#include <string.h>

#define EDGES    800000
#define NNODES   50000
#define HDIM     128
#define K1       384
#define FFDIM    512
#define TEM2     64
#define NTILES   (EDGES / TEM2)
#define GRID_E   148
#define TNN      128
#define NTH      512
#define SCALE_F  30.0f
#define LN_EPS   1e-5f

#define SA2 272

// edge smem layout (bytes)
#define EW1B_OFF 0
#define EW2_OFF  (128 * SA2)                // 34816
#define EW3_OFF  (2 * 128 * SA2)            // 69632
#define EPS_OFF  (3 * 128 * SA2)            // 104448 (fp32 64x132)
#define EX_OFF   (EPS_OFF + 64 * 132 * 4)   // 138240 (hE / X2)
#define EX3_OFF  (EX_OFF + 64 * SA2)        // 155648
#define EDGE_SMEM (EX3_OFF + 64 * SA2)      // 173056

// precompute kernel smem layout
#define PWA_OFF  0
#define PWC_OFF  (128 * SA2)
#define PX_OFF   (2 * 128 * SA2)
#define PST_OFF  (3 * 128 * SA2)
#define PRE_SMEM (PST_OFF + 128 * 132 * 4)  // 172032

// node kernel smem layout
#define HS_STRIDE 132
#define HS_BYTES  (TNN * HS_STRIDE * 4)
#define NX_OFF    HS_BYTES
#define NH_OFF    (NX_OFF + 128 * SA2)
#define NW_OFF    (NH_OFF + 128 * SA2)
#define NODE_SMEM (NW_OFF + 128 * SA2)

__device__ float g_nsum[(size_t)NNODES * HDIM];
__device__ float g_cnt[NNODES];
__device__ float g_pre_s[(size_t)NNODES * HDIM];
__device__ float g_pre_d[(size_t)NNODES * HDIM];

__device__ __forceinline__ float gelu_exact(float x) {
    return 0.5f * x * (1.0f + erff(x * 0.70710678118654752440f));
}
__device__ __forceinline__ uint32_t smem_u32(const void* p) {
    uint32_t a;
    asm("{ .reg .u64 t; cvta.to.shared.u64 t, %1; cvt.u32.u64 %0, t; }" : "=r"(a) : "l"(p));
    return a;
}
__device__ __forceinline__ void ldsm4(uint32_t r[4], uint32_t addr) {
    asm volatile("ldmatrix.sync.aligned.m8n8.x4.shared.b16 {%0,%1,%2,%3}, [%4];"
                 : "=r"(r[0]), "=r"(r[1]), "=r"(r[2]), "=r"(r[3]) : "r"(addr));
}
__device__ __forceinline__ void mma_bf16(float c[4], const uint32_t a[4],
                                         uint32_t b0, uint32_t b1) {
    asm volatile("mma.sync.aligned.m16n8k16.row.col.f32.bf16.bf16.f32 "
                 "{%0,%1,%2,%3}, {%4,%5,%6,%7}, {%8,%9}, {%0,%1,%2,%3};"
                 : "+f"(c[0]), "+f"(c[1]), "+f"(c[2]), "+f"(c[3])
                 : "r"(a[0]), "r"(a[1]), "r"(a[2]), "r"(a[3]), "r"(b0), "r"(b1));
}
__device__ __forceinline__ void st_bf16x4(char* dst, float4 v) {
    __nv_bfloat162 h0 = __floats2bfloat162_rn(v.x, v.y);
    __nv_bfloat162 h1 = __floats2bfloat162_rn(v.z, v.w);
    uint32_t u0, u1;
    memcpy(&u0, &h0, 4); memcpy(&u1, &h1, 4);
    *(uint2*)dst = make_uint2(u0, u1);
}

// generic warp tile: M = 32 (2 x m16), N = NP*16
template <int KTOT, int SA, int SW, int NP>
__device__ __forceinline__ void mma_tile(const char* A, const char* W,
                                         float (&acc)[2][2 * NP][4],
                                         int wm, int wn, int lane) {
    int row_off = (lane & 7) + ((lane >> 3) & 1) * 8;
    int col_off = (lane >> 4) * 8;
#pragma unroll
    for (int k0 = 0; k0 < KTOT; k0 += 16) {
        uint32_t a[2][4];
#pragma unroll
        for (int mi = 0; mi < 2; mi++)
            ldsm4(a[mi], smem_u32(A + (wm * 32 + mi * 16 + row_off) * SA
                                     + (k0 + col_off) * 2));
        uint32_t b[NP][4];
#pragma unroll
        for (int np = 0; np < NP; np++)
            ldsm4(b[np], smem_u32(W + (wn * 16 * NP + np * 16 + row_off) * SW
                                     + (k0 + col_off) * 2));
#pragma unroll
        for (int mi = 0; mi < 2; mi++)
#pragma unroll
            for (int np = 0; np < NP; np++) {
                mma_bf16(acc[mi][2 * np],     a[mi], b[np][0], b[np][2]);
                mma_bf16(acc[mi][2 * np + 1], a[mi], b[np][1], b[np][3]);
            }
    }
}
template <int NP>
__device__ __forceinline__ void init_bias(float (&acc)[2][2 * NP][4],
                                          const float* sb, int wn, int q) {
#pragma unroll
    for (int ni = 0; ni < 2 * NP; ni++) {
        int c = wn * 16 * NP + ni * 8 + q * 2;
        float v0 = sb[c], v1 = sb[c + 1];
#pragma unroll
        for (int mi = 0; mi < 2; mi++) {
            acc[mi][ni][0] = v0; acc[mi][ni][1] = v1;
            acc[mi][ni][2] = v0; acc[mi][ni][3] = v1;
        }
    }
}
template <int NP>
__device__ __forceinline__ void epi_gelu(char* X, float (&acc)[2][2 * NP][4],
                                         int wm, int wn, int g, int q) {
#pragma unroll
    for (int mi = 0; mi < 2; mi++) {
        int r0 = wm * 32 + mi * 16 + g;
#pragma unroll
        for (int ni = 0; ni < 2 * NP; ni++) {
            int c = wn * 16 * NP + ni * 8 + q * 2;
            __nv_bfloat162 h0 = __floats2bfloat162_rn(gelu_exact(acc[mi][ni][0]),
                                                      gelu_exact(acc[mi][ni][1]));
            __nv_bfloat162 h1 = __floats2bfloat162_rn(gelu_exact(acc[mi][ni][2]),
                                                      gelu_exact(acc[mi][ni][3]));
            uint32_t u0, u1;
            memcpy(&u0, &h0, 4); memcpy(&u1, &h1, 4);
            *(uint32_t*)(X + r0 * SA2 + c * 2) = u0;
            *(uint32_t*)(X + (r0 + 8) * SA2 + c * 2) = u1;
        }
    }
}
// store fragments fp32 into a stride-132 float buffer
template <int NP>
__device__ __forceinline__ void frag_to_f32(float* ST, float (&acc)[2][2 * NP][4],
                                            int wm, int wn, int g, int q) {
#pragma unroll
    for (int mi = 0; mi < 2; mi++) {
        int r0 = wm * 32 + mi * 16 + g;
#pragma unroll
        for (int ni = 0; ni < 2 * NP; ni++) {
            int c = wn * 16 * NP + ni * 8 + q * 2;
            *(float2*)(ST + r0 * 132 + c)       = make_float2(acc[mi][ni][0], acc[mi][ni][1]);
            *(float2*)(ST + (r0 + 8) * 132 + c) = make_float2(acc[mi][ni][2], acc[mi][ni][3]);
        }
    }
}

// ============================================================================
// Precompute kernel: pre_s = hV @ W1a^T + b1 ; pre_d = hV @ W1c^T
// (W1a = cols 0..127 of W1, W1c = cols 256..383)
// ============================================================================
__global__ __launch_bounds__(NTH, 1) void pre_kernel(
    const float* __restrict__ hV, const float* __restrict__ W1,
    const float* __restrict__ b1)
{
    extern __shared__ char smem[];
    char*  Wa = smem + PWA_OFF;
    char*  Wc = smem + PWC_OFF;
    char*  X  = smem + PX_OFF;
    float* ST = (float*)(smem + PST_OFF);

    __shared__ float s_b1[HDIM];

    int tid = threadIdx.x;
    int wid = tid >> 5;
    int lane = tid & 31;
    int wm = wid & 3, wn = wid >> 2;     // 4M x 4N, NP=2
    int g = lane >> 2, q = lane & 3;
    int n0 = blockIdx.x * TNN;

    if (tid < HDIM) s_b1[tid] = b1[tid];

#pragma unroll 4
    for (int t = 0; t < 8; t++) {
        int idx = tid + t * NTH;
        int n = idx >> 5, c4 = idx & 31;
        st_bf16x4(Wa + n * SA2 + c4 * 8, *(const float4*)(W1 + (size_t)n * K1 + c4 * 4));
        st_bf16x4(Wc + n * SA2 + c4 * 8, *(const float4*)(W1 + (size_t)n * K1 + 256 + c4 * 4));
        int gn = n0 + n;
        float4 v = make_float4(0.f, 0.f, 0.f, 0.f);
        if (gn < NNODES) v = *(const float4*)(hV + (size_t)gn * HDIM + c4 * 4);
        st_bf16x4(X + n * SA2 + c4 * 8, v);
    }
    __syncthreads();

    float acc_s[2][4][4], acc_d[2][4][4];
    init_bias<2>(acc_s, s_b1, wn, q);
    mma_tile<HDIM, SA2, SA2, 2>(X, Wa, acc_s, wm, wn, lane);
#pragma unroll
    for (int mi = 0; mi < 2; mi++)
#pragma unroll
        for (int ni = 0; ni < 4; ni++)
#pragma unroll
            for (int k = 0; k < 4; k++) acc_d[mi][ni][k] = 0.f;
    mma_tile<HDIM, SA2, SA2, 2>(X, Wc, acc_d, wm, wn, lane);

    // write pre_s
    frag_to_f32<2>(ST, acc_s, wm, wn, g, q);
    __syncthreads();
#pragma unroll 4
    for (int t = 0; t < 32; t++) {
        int idx = tid + t * NTH;
        int n = idx >> 7, o = idx & 127;
        int gn = n0 + n;
        if (gn < NNODES) g_pre_s[(size_t)gn * HDIM + o] = ST[n * 132 + o];
    }
    __syncthreads();
    // write pre_d
    frag_to_f32<2>(ST, acc_d, wm, wn, g, q);
    __syncthreads();
#pragma unroll 4
    for (int t = 0; t < 32; t++) {
        int idx = tid + t * NTH;
        int n = idx >> 7, o = idx & 127;
        int gn = n0 + n;
        if (gn < NNODES) g_pre_d[(size_t)gn * HDIM + o] = ST[n * 132 + o];
    }
}

// prefetch one tile: pre_s[src]+pre_d[dst] pairs and hE, into registers
__device__ __forceinline__ void prefetch_tile(
    size_t e0, const float* __restrict__ hE,
    const int* __restrict__ src, const int* __restrict__ dst,
    int tid, float4 (&ps)[4], float4 (&pd)[4], float4 (&he)[4])
{
#pragma unroll
    for (int t = 0; t < 4; t++) {
        int idx = tid + t * NTH;
        int e = idx >> 5, c4 = idx & 31;
        int s = src[e0 + e];
        int d = dst[e0 + e];
        ps[t] = *(const float4*)(g_pre_s + (size_t)s * HDIM + c4 * 4);
        pd[t] = *(const float4*)(g_pre_d + (size_t)d * HDIM + c4 * 4);
        he[t] = *(const float4*)(hE + (e0 + e) * HDIM + c4 * 4);
    }
}

// ============================================================================
// Edge kernel: factored layer-1 (K=128) + persistent weights + prefetch
// ============================================================================
__global__ __launch_bounds__(NTH, 1) void edge_kernel_p(
    const float* __restrict__ hE,
    const int* __restrict__ src, const int* __restrict__ dst,
    const float* __restrict__ W1, const float* __restrict__ b2w,
    const float* __restrict__ W2, const float* __restrict__ W3,
    const float* __restrict__ b3w)
{
    extern __shared__ char smem[];
    char*  W1s = smem + EW1B_OFF;     // W1b = cols 128..255
    char*  W2s = smem + EW2_OFF;
    char*  W3s = smem + EW3_OFF;
    float* PS  = (float*)(smem + EPS_OFF);
    char*  XB  = smem + EX_OFF;       // hE bf16 -> X2 after epi1
    char*  X3  = smem + EX3_OFF;

    __shared__ int   sidx[2][TEM2];
    __shared__ float s_b2[HDIM], s_b3[HDIM];

    int tid = threadIdx.x;
    int wid = tid >> 5;
    int lane = tid & 31;
    int wm = wid & 1, wn = wid >> 1;     // 2M x 8N, NP=1
    int g = lane >> 2, q = lane & 3;

    if (tid < HDIM) { s_b2[tid] = b2w[tid]; s_b3[tid] = b3w[tid]; }
    // persistent weight staging
#pragma unroll 4
    for (int t = 0; t < 8; t++) {
        int idx = tid + t * NTH;
        int n = idx >> 5, c4 = idx & 31;
        st_bf16x4(W1s + n * SA2 + c4 * 8, *(const float4*)(W1 + (size_t)n * K1 + 128 + c4 * 4));
        st_bf16x4(W2s + n * SA2 + c4 * 8, *(const float4*)(W2 + (size_t)n * HDIM + c4 * 4));
        st_bf16x4(W3s + n * SA2 + c4 * 8, *(const float4*)(W3 + (size_t)n * HDIM + c4 * 4));
    }

    int tile0 = blockIdx.x;
    float4 ps[4], pd[4], he[4];
    {
        size_t e0 = (size_t)tile0 * TEM2;
        if (tid < TEM2) sidx[0][tid] = src[e0 + tid];
        prefetch_tile(e0, hE, src, dst, tid, ps, pd, he);
    }
    __syncthreads();

    int p = 0;
    for (int tile = tile0; tile < NTILES; tile += GRID_E, p ^= 1) {
        const int* si = sidx[p];

        // ---- gather: hE bf16 + PS = pre_s+pre_d fp32 (pure stores) ----
#pragma unroll
        for (int t = 0; t < 4; t++) {
            int idx = tid + t * NTH;
            int e = idx >> 5, c4 = idx & 31;
            st_bf16x4(XB + e * SA2 + c4 * 8, he[t]);
            float4 v = make_float4(ps[t].x + pd[t].x, ps[t].y + pd[t].y,
                                   ps[t].z + pd[t].z, ps[t].w + pd[t].w);
            *(float4*)(PS + e * 132 + c4 * 4) = v;
        }
        __syncthreads();

        // ---- next tile prefetch (hidden under MMA) ----
        int tnext = tile + GRID_E;
        if (tnext < NTILES) {
            size_t e0n = (size_t)tnext * TEM2;
            if (tid < TEM2) sidx[p ^ 1][tid] = src[e0n + tid];
            prefetch_tile(e0n, hE, src, dst, tid, ps, pd, he);
        }

        float acc[2][2][4];

        // layer 1: acc init from PS, K=128 over hE
#pragma unroll
        for (int mi = 0; mi < 2; mi++) {
            int r0 = wm * 32 + mi * 16 + g;
#pragma unroll
            for (int ni = 0; ni < 2; ni++) {
                int c = wn * 16 + ni * 8 + q * 2;
                float2 v0 = *(float2*)(PS + r0 * 132 + c);
                float2 v1 = *(float2*)(PS + (r0 + 8) * 132 + c);
                acc[mi][ni][0] = v0.x; acc[mi][ni][1] = v0.y;
                acc[mi][ni][2] = v1.x; acc[mi][ni][3] = v1.y;
            }
        }
        mma_tile<HDIM, SA2, SA2, 1>(XB, W1s, acc, wm, wn, lane);
        __syncthreads();
        epi_gelu<1>(XB, acc, wm, wn, g, q);          // X2 overwrites hE
        __syncthreads();

        // layer 2
        init_bias<1>(acc, s_b2, wn, q);
        mma_tile<HDIM, SA2, SA2, 1>(XB, W2s, acc, wm, wn, lane);
        epi_gelu<1>(X3, acc, wm, wn, g, q);
        __syncthreads();

        // layer 3
        init_bias<1>(acc, s_b3, wn, q);
        mma_tile<HDIM, SA2, SA2, 1>(X3, W3s, acc, wm, wn, lane);

        // direct scatter (float2 vector atomics)
#pragma unroll
        for (int mi = 0; mi < 2; mi++) {
            int r0 = wm * 32 + mi * 16 + g;
            float* row0 = &g_nsum[(size_t)si[r0] * HDIM];
            float* row1 = &g_nsum[(size_t)si[r0 + 8] * HDIM];
#pragma unroll
            for (int ni = 0; ni < 2; ni++) {
                int c = wn * 16 + ni * 8 + q * 2;
                atomicAdd((float2*)(row0 + c), make_float2(acc[mi][ni][0], acc[mi][ni][1]));
                atomicAdd((float2*)(row1 + c), make_float2(acc[mi][ni][2], acc[mi][ni][3]));
            }
        }
        if (tid < TEM2) atomicAdd(&g_cnt[si[tid]], 1.0f);

        __syncthreads();
    }
}

// ============================================================================
// Node kernel: 512 threads, bf16 mma FFN + fp32 LN / residuals (unchanged)
// ============================================================================
__global__ __launch_bounds__(NTH, 1) void node_kernel_mma(
    const float* __restrict__ hV,
    const float* __restrict__ ln1g, const float* __restrict__ ln1b,
    const float* __restrict__ ln2g, const float* __restrict__ ln2b,
    const float* __restrict__ Win,  const float* __restrict__ bin,
    const float* __restrict__ Wout, const float* __restrict__ bout,
    float* __restrict__ out)
{
    extern __shared__ char smem[];
    float* hs = (float*)smem;
    char*  X  = smem + NX_OFF;
    char*  Hb = smem + NH_OFF;
    char*  Wb = smem + NW_OFF;

    __shared__ float s_bout[HDIM];

    int tid = threadIdx.x;
    int wid = tid >> 5;
    int lane = tid & 31;
    int wm = wid & 3, wn = wid >> 2;
    int g = lane >> 2, q = lane & 3;
    int n0 = blockIdx.x * TNN;

    if (tid < HDIM) s_bout[tid] = bout[tid];

#pragma unroll 4
    for (int t = 0; t < 32; t++) {
        int idx = tid + t * NTH;
        int n = idx >> 7, o = idx & 127;
        int gn = n0 + n;
        float v = 0.0f;
        if (gn < NNODES) {
            float c = fmaxf(g_cnt[gn], 1.0f);
            v = hV[(size_t)gn * HDIM + o] + g_nsum[(size_t)gn * HDIM + o] / (c * SCALE_F);
        }
        hs[n * HS_STRIDE + o] = v;
    }
    __syncthreads();

    {
        int n = tid >> 2, q4 = tid & 3;
        float s = 0.0f, ss = 0.0f;
#pragma unroll
        for (int jj = 0; jj < 32; jj++) {
            float v = hs[n * HS_STRIDE + q4 * 32 + jj];
            s += v; ss += v * v;
        }
#pragma unroll
        for (int m = 1; m < 4; m <<= 1) {
            s  += __shfl_xor_sync(0xffffffffu, s,  m);
            ss += __shfl_xor_sync(0xffffffffu, ss, m);
        }
        float mu   = s * (1.0f / 128.0f);
        float var  = ss * (1.0f / 128.0f) - mu * mu;
        float rstd = rsqrtf(var + LN_EPS);
#pragma unroll
        for (int jj = 0; jj < 32; jj += 2) {
            int o = q4 * 32 + jj;
            float v0 = (hs[n * HS_STRIDE + o]     - mu) * rstd * ln1g[o]     + ln1b[o];
            float v1 = (hs[n * HS_STRIDE + o + 1] - mu) * rstd * ln1g[o + 1] + ln1b[o + 1];
            hs[n * HS_STRIDE + o]     = v0;
            hs[n * HS_STRIDE + o + 1] = v1;
            __nv_bfloat162 hh = __floats2bfloat162_rn(v0, v1);
            uint32_t u; memcpy(&u, &hh, 4);
            *(uint32_t*)(X + n * SA2 + o * 2) = u;
        }
    }

    float dh[2][4][4];
    init_bias<2>(dh, s_bout, wn, q);

    for (int nb = 0; nb < 4; nb++) {
        __syncthreads();
#pragma unroll 4
        for (int t = 0; t < 8; t++) {
            int idx = tid + t * NTH;
            int n = idx >> 5, c4 = idx & 31;
            st_bf16x4(Wb + n * SA2 + c4 * 8,
                      *(const float4*)(Win + (size_t)(nb * 128 + n) * HDIM + c4 * 4));
        }
        __syncthreads();

        float acc[2][4][4];
        init_bias<2>(acc, bin + nb * 128, wn, q);
        mma_tile<HDIM, SA2, SA2, 2>(X, Wb, acc, wm, wn, lane);
        __syncthreads();
        epi_gelu<2>(Hb, acc, wm, wn, g, q);

#pragma unroll 4
        for (int t = 0; t < 8; t++) {
            int idx = tid + t * NTH;
            int n = idx >> 5, c4 = idx & 31;
            st_bf16x4(Wb + n * SA2 + c4 * 8,
                      *(const float4*)(Wout + (size_t)n * FFDIM + nb * 128 + c4 * 4));
        }
        __syncthreads();

        mma_tile<HDIM, SA2, SA2, 2>(Hb, Wb, dh, wm, wn, lane);
    }
    __syncthreads();

    float* zs = (float*)X;
#pragma unroll
    for (int mi = 0; mi < 2; mi++) {
        int r0 = wm * 32 + mi * 16 + g;
#pragma unroll
        for (int ni = 0; ni < 4; ni++) {
            int c = wn * 32 + ni * 8 + q * 2;
            zs[r0 * 132 + c]           = dh[mi][ni][0] + hs[r0 * HS_STRIDE + c];
            zs[r0 * 132 + c + 1]       = dh[mi][ni][1] + hs[r0 * HS_STRIDE + c + 1];
            zs[(r0 + 8) * 132 + c]     = dh[mi][ni][2] + hs[(r0 + 8) * HS_STRIDE + c];
            zs[(r0 + 8) * 132 + c + 1] = dh[mi][ni][3] + hs[(r0 + 8) * HS_STRIDE + c + 1];
        }
    }
    __syncthreads();

    {
        int n = tid >> 2, q4 = tid & 3;
        float s = 0.0f, ss = 0.0f;
#pragma unroll
        for (int jj = 0; jj < 32; jj++) {
            float v = zs[n * 132 + q4 * 32 + jj];
            s += v; ss += v * v;
        }
#pragma unroll
        for (int m = 1; m < 4; m <<= 1) {
            s  += __shfl_xor_sync(0xffffffffu, s,  m);
            ss += __shfl_xor_sync(0xffffffffu, ss, m);
        }
        float mu   = s * (1.0f / 128.0f);
        float var  = ss * (1.0f / 128.0f) - mu * mu;
        float rstd = rsqrtf(var + LN_EPS);
        int gn = n0 + n;
        if (gn < NNODES) {
#pragma unroll
            for (int jj = 0; jj < 32; jj++) {
                int o = q4 * 32 + jj;
                float v = zs[n * 132 + o];
                out[(size_t)gn * HDIM + o] = (v - mu) * rstd * ln2g[o] + ln2b[o];
            }
        }
    }
}

// ============================================================================
// Launch
// ============================================================================
extern "C" void kernel_launch(void* const* d_in, const int* in_sizes, int n_in,
                              void* d_out, int out_size)
{
    const float* hV   = (const float*)d_in[0];
    const float* hE   = (const float*)d_in[1];
    const int*   src  = (const int*)  d_in[2];
    const int*   dst  = (const int*)  d_in[4];
    const float* W1   = (const float*)d_in[5];
    const float* b1   = (const float*)d_in[6];
    const float* W2   = (const float*)d_in[7];
    const float* b2   = (const float*)d_in[8];
    const float* W3   = (const float*)d_in[9];
    const float* b3   = (const float*)d_in[10];
    const float* ln1g = (const float*)d_in[11];
    const float* ln1b = (const float*)d_in[12];
    const float* ln2g = (const float*)d_in[13];
    const float* ln2b = (const float*)d_in[14];
    const float* Win  = (const float*)d_in[15];
    const float* bin  = (const float*)d_in[16];
    const float* Wout = (const float*)d_in[17];
    const float* bout = (const float*)d_in[18];
    float* out = (float*)d_out;

    cudaFuncSetAttribute(pre_kernel, cudaFuncAttributeMaxDynamicSharedMemorySize, PRE_SMEM);
    cudaFuncSetAttribute(edge_kernel_p, cudaFuncAttributeMaxDynamicSharedMemorySize, EDGE_SMEM);
    cudaFuncSetAttribute(node_kernel_mma, cudaFuncAttributeMaxDynamicSharedMemorySize, NODE_SMEM);

    void* nsum_p = nullptr;
    void* cnt_p  = nullptr;
    cudaGetSymbolAddress(&nsum_p, g_nsum);
    cudaGetSymbolAddress(&cnt_p,  g_cnt);
    cudaMemsetAsync(nsum_p, 0, sizeof(float) * (size_t)NNODES * HDIM);
    cudaMemsetAsync(cnt_p,  0, sizeof(float) * NNODES);

    int nblk = (NNODES + TNN - 1) / TNN;
    pre_kernel<<<nblk, NTH, PRE_SMEM>>>(hV, W1, b1);
    edge_kernel_p<<<GRID_E, NTH, EDGE_SMEM>>>(hE, src, dst, W1, b2, W2, W3, b3);
    node_kernel_mma<<<nblk, NTH, NODE_SMEM>>>(
        hV, ln1g, ln1b, ln2g, ln2b, Win, bin, Wout, bout, out);
}